// round 1
// baseline (speedup 1.0000x reference)
#include <cuda_runtime.h>
#include <cstdint>

// Problem constants
#define Bsz 16384
#define Dd  1024
#define Lc  6
#define NMC 64
#define Hh  16

// GEMM tiling (generic)
#define BM 128
#define BN 128
#define BK 16
#define TM 8
#define TN 8

// Fused (exc/inh/lat) kernel tiling
#define FBN 64
#define FTN 4

// Scratch: two [B, D] fp32 buffers (64 MB each). No allocation — device globals.
__device__ float g_mc[(size_t)Bsz * Dd];
__device__ float g_buf[(size_t)Bsz * Dd];

// ---------------------------------------------------------------------------
// Generic GEMM:  C[b,n] = (ACC ? C[b,n] : 0) + sum_k A[b,k]*W[k,n] + bias[n]
// A: [Bsz, Dd] row-major, W: [Dd, Dd] row-major, C: [Bsz, Dd]
// ---------------------------------------------------------------------------
template <bool ACC>
__global__ __launch_bounds__(256, 2)
void gemm_bias(const float* __restrict__ A, const float* __restrict__ W,
               const float* __restrict__ bias, float* __restrict__ C) {
    __shared__ float As[BK][BM + 4];   // padded: conflict-free scatter stores
    __shared__ float Bs[BK][BN];

    const int m0 = blockIdx.y * BM;
    const int n0 = blockIdx.x * BN;
    const int tid = threadIdx.x;
    const int tr = tid >> 4;        // 0..15 (row group of 8)
    const int tc = tid & 15;        // 0..15 (col group of 8)

    float acc[TM][TN] = {};

    for (int k0 = 0; k0 < Dd; k0 += BK) {
        // Load A tile: 128 rows x 16 k = 512 float4 (2 per thread), store transposed
        #pragma unroll
        for (int it = 0; it < 2; it++) {
            int item = tid + it * 256;
            int row = item >> 2;
            int c4  = (item & 3) * 4;
            float4 v = *reinterpret_cast<const float4*>(
                &A[(size_t)(m0 + row) * Dd + k0 + c4]);
            As[c4 + 0][row] = v.x;
            As[c4 + 1][row] = v.y;
            As[c4 + 2][row] = v.z;
            As[c4 + 3][row] = v.w;
        }
        // Load B tile: 16 x 128 = 512 float4 (2 per thread), coalesced
        #pragma unroll
        for (int it = 0; it < 2; it++) {
            int item = tid + it * 256;
            int kk = item >> 5;
            int n4 = (item & 31) * 4;
            *reinterpret_cast<float4*>(&Bs[kk][n4]) =
                *reinterpret_cast<const float4*>(&W[(size_t)(k0 + kk) * Dd + n0 + n4]);
        }
        __syncthreads();

        #pragma unroll
        for (int k = 0; k < BK; k++) {
            float a[TM], b[TN];
            #pragma unroll
            for (int i = 0; i < TM; i++) a[i] = As[k][tr * TM + i];
            #pragma unroll
            for (int j = 0; j < TN; j++) b[j] = Bs[k][tc * TN + j];
            #pragma unroll
            for (int i = 0; i < TM; i++)
                #pragma unroll
                for (int j = 0; j < TN; j++)
                    acc[i][j] += a[i] * b[j];
        }
        __syncthreads();
    }

    // Epilogue: bias (+ optional accumulate with existing C), vectorized store
    #pragma unroll
    for (int i = 0; i < TM; i++) {
        int row = m0 + tr * TM + i;
        #pragma unroll
        for (int j = 0; j < TN; j += 4) {
            int col = n0 + tc * TN + j;
            float4* p = reinterpret_cast<float4*>(&C[(size_t)row * Dd + col]);
            float4 r;
            r.x = acc[i][j + 0] + bias[col + 0];
            r.y = acc[i][j + 1] + bias[col + 1];
            r.z = acc[i][j + 2] + bias[col + 2];
            r.w = acc[i][j + 3] + bias[col + 3];
            if (ACC) {
                float4 o = *p;
                r.x += o.x; r.y += o.y; r.z += o.z; r.w += o.w;
            }
            *p = r;
        }
    }
}

// ---------------------------------------------------------------------------
// Fused minicolumn kernel:
//   exc = relu(x @ We' + be); inh = relu(x @ Wi' + bi)
//   lat[b,m,k] = sum_h inh[b,m,h]*Wl[m,h,k] + bl[m,k]
//   mc  = relu(exc - lat)
// where We'[d, m*H+h] = We[m,d,h].
// Tile: BM=128 x FBN=64 (4 minicolumns), dual accumulators.
// ---------------------------------------------------------------------------
__global__ __launch_bounds__(256, 1)
void fused_mc(const float* __restrict__ x,
              const float* __restrict__ We_l, const float* __restrict__ be_l,
              const float* __restrict__ Wi_l, const float* __restrict__ bi_l,
              const float* __restrict__ Wl_l, const float* __restrict__ bl_l,
              float* __restrict__ mc) {
    __shared__ union {
        struct {
            float As[BK][BM + 4];
            float Be[BK][FBN];
            float Bi[BK][FBN];
        } load;                              // 16.25 KB
        struct {
            float inh[BM][FBN + 8];          // +8 pad
            float Wl[NMC / 16 * 4 * 256];    // 4 minicolumns x 16x16
            float bl[FBN];
        } epi;                               // ~41 KB
    } sm;

    const int m0 = blockIdx.y * BM;
    const int n0 = blockIdx.x * FBN;
    const int tid = threadIdx.x;
    const int tr = tid >> 4;        // 0..15 -> rows of 8
    const int tc = tid & 15;        // 0..15 -> cols of 4

    float acc_e[TM][FTN] = {};
    float acc_i[TM][FTN] = {};

    for (int k0 = 0; k0 < Dd; k0 += BK) {
        // A tile (same as generic)
        #pragma unroll
        for (int it = 0; it < 2; it++) {
            int item = tid + it * 256;
            int row = item >> 2;
            int c4  = (item & 3) * 4;
            float4 v = *reinterpret_cast<const float4*>(
                &x[(size_t)(m0 + row) * Dd + k0 + c4]);
            sm.load.As[c4 + 0][row] = v.x;
            sm.load.As[c4 + 1][row] = v.y;
            sm.load.As[c4 + 2][row] = v.z;
            sm.load.As[c4 + 3][row] = v.w;
        }
        // We / Wi tiles: column j = m*16+h -> element We[m, d, h] = We_l[(m*D+d)*16 + h]
        {
            int kk = tid >> 4;           // 0..15
            int n  = (tid & 15) * 4;     // 0..60, h-aligned to 4
            int col = n0 + n;
            int m = col >> 4;
            int h = col & 15;
            size_t off = ((size_t)m * Dd + (k0 + kk)) * Hh + h;
            *reinterpret_cast<float4*>(&sm.load.Be[kk][n]) =
                *reinterpret_cast<const float4*>(&We_l[off]);
            *reinterpret_cast<float4*>(&sm.load.Bi[kk][n]) =
                *reinterpret_cast<const float4*>(&Wi_l[off]);
        }
        __syncthreads();

        #pragma unroll
        for (int k = 0; k < BK; k++) {
            float a[TM], beF[FTN], biF[FTN];
            #pragma unroll
            for (int i = 0; i < TM; i++) a[i] = sm.load.As[k][tr * TM + i];
            #pragma unroll
            for (int j = 0; j < FTN; j++) {
                beF[j] = sm.load.Be[k][tc * FTN + j];
                biF[j] = sm.load.Bi[k][tc * FTN + j];
            }
            #pragma unroll
            for (int i = 0; i < TM; i++) {
                #pragma unroll
                for (int j = 0; j < FTN; j++) {
                    acc_e[i][j] += a[i] * beF[j];
                    acc_i[i][j] += a[i] * biF[j];
                }
            }
        }
        __syncthreads();
    }

    // bias + relu; keep exc in regs, stash inh in smem
    #pragma unroll
    for (int i = 0; i < TM; i++) {
        int row_l = tr * TM + i;
        #pragma unroll
        for (int j = 0; j < FTN; j++) {
            int cl = tc * FTN + j;
            int col = n0 + cl;
            float e = fmaxf(acc_e[i][j] + be_l[col], 0.0f);
            float v = fmaxf(acc_i[i][j] + bi_l[col], 0.0f);
            acc_e[i][j] = e;
            sm.epi.inh[row_l][cl] = v;
        }
    }
    // Wl for the 4 minicolumns of this tile: contiguous 1024 floats at Wl_l[n0*16]
    {
        *reinterpret_cast<float4*>(&sm.epi.Wl[tid * 4]) =
            *reinterpret_cast<const float4*>(&Wl_l[(size_t)n0 * Hh + tid * 4]);
        if (tid < FBN) sm.epi.bl[tid] = bl_l[n0 + tid];
    }
    __syncthreads();

    // lateral inhibition + final relu + store
    #pragma unroll
    for (int i = 0; i < TM; i++) {
        int row_l = tr * TM + i;
        float4 r;
        float* rp = &r.x;
        #pragma unroll
        for (int j = 0; j < FTN; j++) {
            int cl = tc * FTN + j;
            int ml = cl >> 4;
            int kk = cl & 15;
            float lat = sm.epi.bl[cl];
            const float* ih = &sm.epi.inh[row_l][ml * 16];
            const float* wl = &sm.epi.Wl[ml * 256 + kk];
            #pragma unroll
            for (int h = 0; h < Hh; h++) lat += ih[h] * wl[h * 16];
            rp[j] = fmaxf(acc_e[i][j] - lat, 0.0f);
        }
        *reinterpret_cast<float4*>(&mc[(size_t)(m0 + row_l) * Dd + n0 + tc * FTN]) = r;
    }
}

// ---------------------------------------------------------------------------
// Host orchestration
// ---------------------------------------------------------------------------
extern "C" void kernel_launch(void* const* d_in, const int* in_sizes, int n_in,
                              void* d_out, int out_size) {
    const float* x    = (const float*)d_in[0];
    const float* We   = (const float*)d_in[1];
    const float* be   = (const float*)d_in[2];
    const float* Wi   = (const float*)d_in[3];
    const float* bi   = (const float*)d_in[4];
    const float* Wl   = (const float*)d_in[5];
    const float* bl   = (const float*)d_in[6];
    const float* Wlat = (const float*)d_in[7];
    const float* blat = (const float*)d_in[8];
    const float* Wv   = (const float*)d_in[9];
    const float* bv   = (const float*)d_in[10];
    const float* Wo   = (const float*)d_in[11];
    const float* bo   = (const float*)d_in[12];
    const float* fbW  = (const float*)d_in[13];
    const float* fbb  = (const float*)d_in[14];
    float* out = (float*)d_out;

    float *mc = nullptr, *buf = nullptr;
    cudaGetSymbolAddress((void**)&mc, g_mc);
    cudaGetSymbolAddress((void**)&buf, g_buf);

    const size_t WSTRIDE = (size_t)Dd * Dd;          // 1M floats per layer weight
    const size_t WE_STRIDE = (size_t)NMC * Dd * Hh;  // == 1M
    const size_t WL_STRIDE = (size_t)NMC * Hh * Hh;  // 16K
    const size_t BD = (size_t)Bsz * Dd;

    dim3 gridF(Dd / FBN, Bsz / BM);   // 16 x 128
    dim3 gridG(Dd / BN, Bsz / BM);    // 8 x 128

    const float* carry = x;
    for (int l = 0; l < Lc; l++) {
        fused_mc<<<gridF, 256>>>(carry,
                                 We + l * WE_STRIDE, be + l * Dd,
                                 Wi + l * WE_STRIDE, bi + l * Dd,
                                 Wl + l * WL_STRIDE, bl + l * Dd, mc);
        gemm_bias<false><<<gridG, 256>>>(mc,  Wlat + l * WSTRIDE, blat + l * Dd, buf);
        gemm_bias<false><<<gridG, 256>>>(buf, Wv   + l * WSTRIDE, bv   + l * Dd, mc);
        gemm_bias<false><<<gridG, 256>>>(mc,  Wo   + l * WSTRIDE, bo   + l * Dd,
                                         out + (size_t)l * BD);
        carry = out + (size_t)l * BD;
    }

    // Feedback chain (serial): out[idx] += fb_in @ fbW[i] + fbb[i]
    const float* fb_in = out + (size_t)(Lc - 1) * BD;
    for (int i = 0; i < Lc - 1; i++) {
        int idx = Lc - 2 - i;
        gemm_bias<true><<<gridG, 256>>>(fb_in, fbW + i * WSTRIDE, fbb + i * Dd,
                                        out + (size_t)idx * BD);
        fb_in = out + (size_t)idx * BD;
    }
}

// round 2
// speedup vs baseline: 2.2314x; 2.2314x over previous
#include <cuda_runtime.h>
#include <cuda_bf16.h>
#include <mma.h>
#include <cstdint>

using namespace nvcuda;

// Problem constants
#define Bsz 16384
#define Dd  1024
#define Lc  6
#define NMC 64
#define Hh  16

// GEMM tiling
#define BM  128
#define BN  128
#define BKK 32
#define ALD (BKK + 8)   // 40  (A smem row stride, elements)
#define BLD (BN + 8)    // 136 (B smem row stride, elements)

// Fused kernel tiling
#define FN   64
#define FBLD (FN + 8)   // 72

// Scratch buffers (device globals; no allocation)
__device__ float g_mc [(size_t)Bsz * Dd];
__device__ float g_buf[(size_t)Bsz * Dd];

// Split two fp32 into bf16 (hi, lo) pairs
__device__ __forceinline__ void split2(float a, float b,
                                       __nv_bfloat162* hi, __nv_bfloat162* lo) {
    __nv_bfloat16 ha = __float2bfloat16(a);
    __nv_bfloat16 hb = __float2bfloat16(b);
    float ra = a - __bfloat162float(ha);
    float rb = b - __bfloat162float(hb);
    __nv_bfloat162 h; h.x = ha; h.y = hb;
    __nv_bfloat162 l; l.x = __float2bfloat16(ra); l.y = __float2bfloat16(rb);
    *hi = h; *lo = l;
}

// ---------------------------------------------------------------------------
// Generic GEMM (bf16x2 split, fp32 accum):
//   C = (ACC ? C : 0) + A @ W + bias
// A:[Bsz,Dd] rm, W:[Dd,Dd] rm, C:[Bsz,Dd]
// ---------------------------------------------------------------------------
template <bool ACC>
__global__ __launch_bounds__(256, 2)
void gemm_wmma(const float* __restrict__ A, const float* __restrict__ W,
               const float* __restrict__ bias, float* __restrict__ C) {
    __shared__ __nv_bfloat16 Ah[BM][ALD];
    __shared__ __nv_bfloat16 Al[BM][ALD];
    __shared__ __nv_bfloat16 Bh[BKK][BLD];
    __shared__ __nv_bfloat16 Bl[BKK][BLD];
    __shared__ float biasrep[16][BLD];

    const int m0 = blockIdx.y * BM;
    const int n0 = blockIdx.x * BN;
    const int tid = threadIdx.x;
    const int wid = tid >> 5;
    const int wm = wid >> 2;     // 0..1 : 64-row band
    const int wn = wid & 3;      // 0..3 : 32-col band

    // Replicate bias across 16 rows for accumulator-fragment init
    #pragma unroll
    for (int it = 0; it < 8; it++) {
        int item = tid + it * 256;            // 0..2047
        biasrep[item >> 7][item & 127] = bias[n0 + (item & 127)];
    }
    __syncthreads();

    wmma::fragment<wmma::accumulator, 16, 16, 16, float> acc[4][2];
    #pragma unroll
    for (int i = 0; i < 4; i++) {
        #pragma unroll
        for (int j = 0; j < 2; j++) {
            wmma::load_matrix_sync(acc[i][j], &biasrep[0][wn * 32 + j * 16],
                                   BLD, wmma::mem_row_major);
            if (ACC) {
                wmma::fragment<wmma::accumulator, 16, 16, 16, float> old;
                wmma::load_matrix_sync(old,
                    &C[(size_t)(m0 + wm * 64 + i * 16) * Dd + n0 + wn * 32 + j * 16],
                    Dd, wmma::mem_row_major);
                #pragma unroll
                for (int e = 0; e < old.num_elements; e++)
                    acc[i][j].x[e] += old.x[e];
            }
        }
    }

    for (int k0 = 0; k0 < Dd; k0 += BKK) {
        // A tile: 128x32 fp32 -> split bf16 (1024 float4, 4/thread)
        #pragma unroll
        for (int it = 0; it < 4; it++) {
            int item = tid + it * 256;
            int row = item >> 3;
            int c = (item & 7) * 4;
            float4 v = *reinterpret_cast<const float4*>(
                &A[(size_t)(m0 + row) * Dd + k0 + c]);
            __nv_bfloat162 h0, h1, l0, l1;
            split2(v.x, v.y, &h0, &l0);
            split2(v.z, v.w, &h1, &l1);
            *reinterpret_cast<__nv_bfloat162*>(&Ah[row][c])     = h0;
            *reinterpret_cast<__nv_bfloat162*>(&Ah[row][c + 2]) = h1;
            *reinterpret_cast<__nv_bfloat162*>(&Al[row][c])     = l0;
            *reinterpret_cast<__nv_bfloat162*>(&Al[row][c + 2]) = l1;
        }
        // B tile: 32x128
        #pragma unroll
        for (int it = 0; it < 4; it++) {
            int item = tid + it * 256;
            int row = item >> 5;
            int c = (item & 31) * 4;
            float4 v = *reinterpret_cast<const float4*>(
                &W[(size_t)(k0 + row) * Dd + n0 + c]);
            __nv_bfloat162 h0, h1, l0, l1;
            split2(v.x, v.y, &h0, &l0);
            split2(v.z, v.w, &h1, &l1);
            *reinterpret_cast<__nv_bfloat162*>(&Bh[row][c])     = h0;
            *reinterpret_cast<__nv_bfloat162*>(&Bh[row][c + 2]) = h1;
            *reinterpret_cast<__nv_bfloat162*>(&Bl[row][c])     = l0;
            *reinterpret_cast<__nv_bfloat162*>(&Bl[row][c + 2]) = l1;
        }
        __syncthreads();

        #pragma unroll
        for (int ks = 0; ks < BKK; ks += 16) {
            wmma::fragment<wmma::matrix_b, 16, 16, 16, __nv_bfloat16, wmma::row_major> bh[2], bl[2];
            #pragma unroll
            for (int j = 0; j < 2; j++) {
                wmma::load_matrix_sync(bh[j], &Bh[ks][wn * 32 + j * 16], BLD);
                wmma::load_matrix_sync(bl[j], &Bl[ks][wn * 32 + j * 16], BLD);
            }
            #pragma unroll
            for (int i = 0; i < 4; i++) {
                wmma::fragment<wmma::matrix_a, 16, 16, 16, __nv_bfloat16, wmma::row_major> ah, al;
                wmma::load_matrix_sync(ah, &Ah[wm * 64 + i * 16][ks], ALD);
                wmma::load_matrix_sync(al, &Al[wm * 64 + i * 16][ks], ALD);
                #pragma unroll
                for (int j = 0; j < 2; j++) {
                    wmma::mma_sync(acc[i][j], ah, bh[j], acc[i][j]);
                    wmma::mma_sync(acc[i][j], ah, bl[j], acc[i][j]);
                    wmma::mma_sync(acc[i][j], al, bh[j], acc[i][j]);
                }
            }
        }
        __syncthreads();
    }

    #pragma unroll
    for (int i = 0; i < 4; i++) {
        #pragma unroll
        for (int j = 0; j < 2; j++) {
            wmma::store_matrix_sync(
                &C[(size_t)(m0 + wm * 64 + i * 16) * Dd + n0 + wn * 32 + j * 16],
                acc[i][j], Dd, wmma::mem_row_major);
        }
    }
}

// ---------------------------------------------------------------------------
// Fused minicolumn kernel (bf16x2 split GEMMs + fp32 epilogue):
//   exc = relu(x @ We' + be); inh = relu(x @ Wi' + bi)
//   lat = inh @ Wl + bl  (per minicolumn 16x16)
//   mc  = relu(exc - lat)
// We'[d, m*H+h] = We[m,d,h]. Block: 128 rows x 64 cols (4 minicolumns).
// ---------------------------------------------------------------------------
__global__ __launch_bounds__(256, 2)
void fused_mc_wmma(const float* __restrict__ x,
                   const float* __restrict__ We_l, const float* __restrict__ be_l,
                   const float* __restrict__ Wi_l, const float* __restrict__ bi_l,
                   const float* __restrict__ Wl_l, const float* __restrict__ bl_l,
                   float* __restrict__ mc) {
    extern __shared__ char smraw[];
    // Load-stage layout (bf16)
    __nv_bfloat16* Ah  = reinterpret_cast<__nv_bfloat16*>(smraw);    // BM*ALD
    __nv_bfloat16* Al  = Ah  + BM * ALD;
    __nv_bfloat16* Beh = Al  + BM * ALD;                             // BKK*FBLD each
    __nv_bfloat16* Bel = Beh + BKK * FBLD;
    __nv_bfloat16* Bih = Bel + BKK * FBLD;
    __nv_bfloat16* Bil = Bih + BKK * FBLD;
    // Epilogue layout (fp32), aliases the load stage
    float* exc_s = reinterpret_cast<float*>(smraw);                  // BM*FBLD
    float* inh_s = exc_s + BM * FBLD;
    float* wl_s  = inh_s + BM * FBLD;                                // 4*16*16

    const int m0 = blockIdx.y * BM;
    const int n0 = blockIdx.x * FN;
    const int tid = threadIdx.x;
    const int wid = tid >> 5;
    const int wm = wid >> 2;    // 0..1
    const int wn = wid & 3;     // 0..3 -> 16-col band

    wmma::fragment<wmma::accumulator, 16, 16, 16, float> acc_e[4], acc_i[4];
    #pragma unroll
    for (int i = 0; i < 4; i++) {
        wmma::fill_fragment(acc_e[i], 0.0f);
        wmma::fill_fragment(acc_i[i], 0.0f);
    }

    for (int k0 = 0; k0 < Dd; k0 += BKK) {
        // A tile 128x32
        #pragma unroll
        for (int it = 0; it < 4; it++) {
            int item = tid + it * 256;
            int row = item >> 3;
            int c = (item & 7) * 4;
            float4 v = *reinterpret_cast<const float4*>(
                &x[(size_t)(m0 + row) * Dd + k0 + c]);
            __nv_bfloat162 h0, h1, l0, l1;
            split2(v.x, v.y, &h0, &l0);
            split2(v.z, v.w, &h1, &l1);
            *reinterpret_cast<__nv_bfloat162*>(&Ah[row * ALD + c])     = h0;
            *reinterpret_cast<__nv_bfloat162*>(&Ah[row * ALD + c + 2]) = h1;
            *reinterpret_cast<__nv_bfloat162*>(&Al[row * ALD + c])     = l0;
            *reinterpret_cast<__nv_bfloat162*>(&Al[row * ALD + c + 2]) = l1;
        }
        // We / Wi gathered tiles: 32 k-rows x 64 cols, col = m*16+h
        // item 0..511: kk=item>>4, n=(item&15)*4
        #pragma unroll
        for (int it = 0; it < 2; it++) {
            int item = tid + it * 256;
            int kk = item >> 4;
            int n = (item & 15) * 4;
            int col = n0 + n;
            int m = col >> 4;
            int h = col & 15;
            size_t off = ((size_t)m * Dd + (k0 + kk)) * Hh + h;
            float4 v = *reinterpret_cast<const float4*>(&We_l[off]);
            __nv_bfloat162 h0, h1, l0, l1;
            split2(v.x, v.y, &h0, &l0);
            split2(v.z, v.w, &h1, &l1);
            *reinterpret_cast<__nv_bfloat162*>(&Beh[kk * FBLD + n])     = h0;
            *reinterpret_cast<__nv_bfloat162*>(&Beh[kk * FBLD + n + 2]) = h1;
            *reinterpret_cast<__nv_bfloat162*>(&Bel[kk * FBLD + n])     = l0;
            *reinterpret_cast<__nv_bfloat162*>(&Bel[kk * FBLD + n + 2]) = l1;
        }
        #pragma unroll
        for (int it = 0; it < 2; it++) {
            int item = tid + it * 256;
            int kk = item >> 4;
            int n = (item & 15) * 4;
            int col = n0 + n;
            int m = col >> 4;
            int h = col & 15;
            size_t off = ((size_t)m * Dd + (k0 + kk)) * Hh + h;
            float4 v = *reinterpret_cast<const float4*>(&Wi_l[off]);
            __nv_bfloat162 h0, h1, l0, l1;
            split2(v.x, v.y, &h0, &l0);
            split2(v.z, v.w, &h1, &l1);
            *reinterpret_cast<__nv_bfloat162*>(&Bih[kk * FBLD + n])     = h0;
            *reinterpret_cast<__nv_bfloat162*>(&Bih[kk * FBLD + n + 2]) = h1;
            *reinterpret_cast<__nv_bfloat162*>(&Bil[kk * FBLD + n])     = l0;
            *reinterpret_cast<__nv_bfloat162*>(&Bil[kk * FBLD + n + 2]) = l1;
        }
        __syncthreads();

        #pragma unroll
        for (int ks = 0; ks < BKK; ks += 16) {
            wmma::fragment<wmma::matrix_b, 16, 16, 16, __nv_bfloat16, wmma::row_major> beh, bel, bih, bil;
            wmma::load_matrix_sync(beh, &Beh[ks * FBLD + wn * 16], FBLD);
            wmma::load_matrix_sync(bel, &Bel[ks * FBLD + wn * 16], FBLD);
            wmma::load_matrix_sync(bih, &Bih[ks * FBLD + wn * 16], FBLD);
            wmma::load_matrix_sync(bil, &Bil[ks * FBLD + wn * 16], FBLD);
            #pragma unroll
            for (int i = 0; i < 4; i++) {
                wmma::fragment<wmma::matrix_a, 16, 16, 16, __nv_bfloat16, wmma::row_major> ah, al;
                wmma::load_matrix_sync(ah, &Ah[(wm * 64 + i * 16) * ALD + ks], ALD);
                wmma::load_matrix_sync(al, &Al[(wm * 64 + i * 16) * ALD + ks], ALD);
                wmma::mma_sync(acc_e[i], ah, beh, acc_e[i]);
                wmma::mma_sync(acc_e[i], ah, bel, acc_e[i]);
                wmma::mma_sync(acc_e[i], al, beh, acc_e[i]);
                wmma::mma_sync(acc_i[i], ah, bih, acc_i[i]);
                wmma::mma_sync(acc_i[i], ah, bil, acc_i[i]);
                wmma::mma_sync(acc_i[i], al, bih, acc_i[i]);
            }
        }
        __syncthreads();
    }

    // Stage raw exc/inh into smem (fp32), load Wl
    #pragma unroll
    for (int i = 0; i < 4; i++) {
        wmma::store_matrix_sync(&exc_s[(wm * 64 + i * 16) * FBLD + wn * 16],
                                acc_e[i], FBLD, wmma::mem_row_major);
        wmma::store_matrix_sync(&inh_s[(wm * 64 + i * 16) * FBLD + wn * 16],
                                acc_i[i], FBLD, wmma::mem_row_major);
    }
    *reinterpret_cast<float4*>(&wl_s[tid * 4]) =
        *reinterpret_cast<const float4*>(&Wl_l[(size_t)(n0 >> 4) * 256 + tid * 4]);
    __syncthreads();

    // Epilogue: bias+relu, lateral inhibition, final relu, store
    const int b = tid >> 1;
    const int c0 = (tid & 1) * 32;
    #pragma unroll
    for (int mcq = 0; mcq < 2; mcq++) {
        int ml = (c0 >> 4) + mcq;          // 0..3 local minicolumn
        float ihv[16];
        #pragma unroll
        for (int h = 0; h < 16; h++)
            ihv[h] = fmaxf(inh_s[b * FBLD + ml * 16 + h] + bi_l[n0 + ml * 16 + h], 0.0f);
        #pragma unroll
        for (int kq = 0; kq < 4; kq++) {
            float4 r;
            float* rp = &r.x;
            #pragma unroll
            for (int e = 0; e < 4; e++) {
                int k = kq * 4 + e;
                int col = n0 + ml * 16 + k;
                float lat = bl_l[col];
                #pragma unroll
                for (int h = 0; h < 16; h++)
                    lat += ihv[h] * wl_s[ml * 256 + h * 16 + k];
                float ex = fmaxf(exc_s[b * FBLD + ml * 16 + k] + be_l[col], 0.0f);
                rp[e] = fmaxf(ex - lat, 0.0f);
            }
            *reinterpret_cast<float4*>(
                &mc[(size_t)(m0 + b) * Dd + n0 + ml * 16 + kq * 4]) = r;
        }
    }
}

// ---------------------------------------------------------------------------
// Host orchestration
// ---------------------------------------------------------------------------
extern "C" void kernel_launch(void* const* d_in, const int* in_sizes, int n_in,
                              void* d_out, int out_size) {
    const float* x    = (const float*)d_in[0];
    const float* We   = (const float*)d_in[1];
    const float* be   = (const float*)d_in[2];
    const float* Wi   = (const float*)d_in[3];
    const float* bi   = (const float*)d_in[4];
    const float* Wl   = (const float*)d_in[5];
    const float* bl   = (const float*)d_in[6];
    const float* Wlat = (const float*)d_in[7];
    const float* blat = (const float*)d_in[8];
    const float* Wv   = (const float*)d_in[9];
    const float* bv   = (const float*)d_in[10];
    const float* Wo   = (const float*)d_in[11];
    const float* bo   = (const float*)d_in[12];
    const float* fbW  = (const float*)d_in[13];
    const float* fbb  = (const float*)d_in[14];
    float* out = (float*)d_out;

    float *mc = nullptr, *buf = nullptr;
    cudaGetSymbolAddress((void**)&mc, g_mc);
    cudaGetSymbolAddress((void**)&buf, g_buf);

    const int FUSED_SMEM = (BM * FBLD + BM * FBLD + NMC / 16 * 4 * 256 / 4 + 1024) * 4;
    // exc + inh + wl (1024 floats) -> compute precisely:
    const int fused_smem = (BM * FBLD * 2 + 1024) * (int)sizeof(float);  // 77,824 B
    (void)FUSED_SMEM;
    cudaFuncSetAttribute(fused_mc_wmma,
                         cudaFuncAttributeMaxDynamicSharedMemorySize, fused_smem);

    const size_t WSTRIDE   = (size_t)Dd * Dd;
    const size_t WE_STRIDE = (size_t)NMC * Dd * Hh;
    const size_t WL_STRIDE = (size_t)NMC * Hh * Hh;
    const size_t BD = (size_t)Bsz * Dd;

    dim3 gridF(Dd / FN, Bsz / BM);    // 16 x 128
    dim3 gridG(Dd / BN, Bsz / BM);    // 8 x 128

    const float* carry = x;
    for (int l = 0; l < Lc; l++) {
        fused_mc_wmma<<<gridF, 256, fused_smem>>>(carry,
            We + l * WE_STRIDE, be + l * Dd,
            Wi + l * WE_STRIDE, bi + l * Dd,
            Wl + l * WL_STRIDE, bl + l * Dd, mc);
        gemm_wmma<false><<<gridG, 256>>>(mc,  Wlat + l * WSTRIDE, blat + l * Dd, buf);
        gemm_wmma<false><<<gridG, 256>>>(buf, Wv   + l * WSTRIDE, bv   + l * Dd, mc);
        gemm_wmma<false><<<gridG, 256>>>(mc,  Wo   + l * WSTRIDE, bo   + l * Dd,
                                         out + (size_t)l * BD);
        carry = out + (size_t)l * BD;
    }

    const float* fb_in = out + (size_t)(Lc - 1) * BD;
    for (int i = 0; i < Lc - 1; i++) {
        int idx = Lc - 2 - i;
        gemm_wmma<true><<<gridG, 256>>>(fb_in, fbW + i * WSTRIDE, fbb + i * Dd,
                                        out + (size_t)idx * BD);
        fb_in = out + (size_t)idx * BD;
    }
}

// round 3
// speedup vs baseline: 2.2608x; 1.0132x over previous
#include <cuda_runtime.h>
#include <cuda_bf16.h>
#include <mma.h>
#include <cstdint>

using namespace nvcuda;
typedef __nv_bfloat16  bf16;
typedef __nv_bfloat162 bf162;

// Problem constants
#define Bsz 16384
#define Dd  1024
#define Lc  6
#define NMC 64
#define Hh  16

// GEMM tiling
#define BM  128
#define BN  128
#define BK  32
#define ALD 40     // A smem row stride (elems), 80B (16B-mult)
#define BLD 136    // B smem row stride, 272B
// Fused kernel tiling
#define FN   64
#define FBLD 72    // 144B

#define M1 (1024 * 1024)
#define BD ((size_t)Bsz * Dd)

// Persistent bf16 split weights (converted once per launch)
__device__ bf16 g_wlat_h[6 * M1], g_wlat_l[6 * M1];
__device__ bf16 g_wv_h  [6 * M1], g_wv_l  [6 * M1];
__device__ bf16 g_wo_h  [6 * M1], g_wo_l  [6 * M1];
__device__ bf16 g_fb_h  [5 * M1], g_fb_l  [5 * M1];
__device__ bf16 g_we_h  [6 * M1], g_we_l  [6 * M1];   // gathered: [d][m*16+h]
__device__ bf16 g_wi_h  [6 * M1], g_wi_l  [6 * M1];
// Activation ping-pong pairs (bf16 split)
__device__ bf16 g_a0h[BD], g_a0l[BD], g_a1h[BD], g_a1l[BD];

// ---------------------------------------------------------------------------
__device__ __forceinline__ void split2(float a, float b, bf162* hi, bf162* lo) {
    bf16 ha = __float2bfloat16(a);
    bf16 hb = __float2bfloat16(b);
    bf162 h; h.x = ha; h.y = hb;
    bf162 l; l.x = __float2bfloat16(a - __bfloat162float(ha));
    l.y = __float2bfloat16(b - __bfloat162float(hb));
    *hi = h; *lo = l;
}

__device__ __forceinline__ void cp16(bf16* smem, const bf16* g) {
    uint32_t s = (uint32_t)__cvta_generic_to_shared(smem);
    asm volatile("cp.async.cg.shared.global [%0], [%1], 16;" :: "r"(s), "l"(g));
}
__device__ __forceinline__ void cp_commit() {
    asm volatile("cp.async.commit_group;");
}
template <int N>
__device__ __forceinline__ void cp_wait() {
    asm volatile("cp.async.wait_group %0;" :: "n"(N));
}

// ---------------------------------------------------------------------------
// Weight / activation conversion kernels
// ---------------------------------------------------------------------------
__global__ void conv_mat(const float* __restrict__ src, bf16* __restrict__ hi,
                         bf16* __restrict__ lo) {
    size_t i = (size_t)blockIdx.x * blockDim.x + threadIdx.x;   // float4 index
    float4 v = reinterpret_cast<const float4*>(src)[i];
    bf162 h0, h1, l0, l1;
    split2(v.x, v.y, &h0, &l0);
    split2(v.z, v.w, &h1, &l1);
    reinterpret_cast<bf162*>(hi)[2 * i]     = h0;
    reinterpret_cast<bf162*>(hi)[2 * i + 1] = h1;
    reinterpret_cast<bf162*>(lo)[2 * i]     = l0;
    reinterpret_cast<bf162*>(lo)[2 * i + 1] = l1;
}

// Gather + convert We/Wi: dst[l][d][m*16+h] = src[l][m][d][h]
__global__ void conv_gather(const float* __restrict__ src, bf16* __restrict__ hi,
                            bf16* __restrict__ lo) {
    int l = blockIdx.y;
    int i = blockIdx.x * blockDim.x + threadIdx.x;   // 0..262143
    int d = i >> 8;
    int c = (i & 255) * 4;          // col in [0,1024), h-aligned to 4
    int m = c >> 4, h = c & 15;
    float4 v = *reinterpret_cast<const float4*>(
        &src[((size_t)l * NMC * Dd + (size_t)m * Dd + d) * Hh + h]);
    bf162 h0, h1, l0, l1;
    split2(v.x, v.y, &h0, &l0);
    split2(v.z, v.w, &h1, &l1);
    size_t o = ((size_t)l * M1 + (size_t)d * Dd + c) >> 1;
    reinterpret_cast<bf162*>(hi)[o]     = h0;
    reinterpret_cast<bf162*>(hi)[o + 1] = h1;
    reinterpret_cast<bf162*>(lo)[o]     = l0;
    reinterpret_cast<bf162*>(lo)[o + 1] = l1;
}

// ---------------------------------------------------------------------------
// Generic GEMM, bf16 split inputs, cp.async double-buffered.
//   C = (ACC ? Cf : 0) + A @ W + bias ;  writes split(C) -> Chi/Clo, fp32 if WF32
// ---------------------------------------------------------------------------
#define GSTG 18944   // elems per stage: 2*5120 + 2*4352
#define GSMEM (2 * GSTG * 2)   // bytes = 75776

template <bool ACC, bool WF32>
__global__ __launch_bounds__(256, 2)
void gemm_bf(const bf16* __restrict__ Ahi, const bf16* __restrict__ Alo,
             const bf16* __restrict__ Whi, const bf16* __restrict__ Wlo,
             const float* __restrict__ bias, float* __restrict__ Cf,
             bf16* __restrict__ Chi, bf16* __restrict__ Clo) {
    extern __shared__ char smraw[];
    bf16* S = reinterpret_cast<bf16*>(smraw);

    const int m0 = blockIdx.y * BM;
    const int n0 = blockIdx.x * BN;
    const int tid = threadIdx.x;
    const int wid = tid >> 5;
    const int wm = wid >> 2;     // 0..1
    const int wn = wid & 3;      // 0..3

    wmma::fragment<wmma::accumulator, 16, 16, 16, float> acc[4][2];
    #pragma unroll
    for (int i = 0; i < 4; i++)
        #pragma unroll
        for (int j = 0; j < 2; j++)
            wmma::fill_fragment(acc[i][j], 0.0f);

    auto load_stage = [&](int s, int k0) {
        bf16* Ah = S + s * GSTG;
        bf16* Al = Ah + 5120;
        bf16* Bh = Al + 5120;
        bf16* Bl = Bh + 4352;
        #pragma unroll
        for (int it = 0; it < 2; it++) {
            int item = tid + it * 256;
            int r = item >> 2, c = (item & 3) * 8;
            cp16(Ah + r * ALD + c, Ahi + (size_t)(m0 + r) * Dd + k0 + c);
            cp16(Al + r * ALD + c, Alo + (size_t)(m0 + r) * Dd + k0 + c);
        }
        #pragma unroll
        for (int it = 0; it < 2; it++) {
            int item = tid + it * 256;
            int r = item >> 4, c = (item & 15) * 8;
            cp16(Bh + r * BLD + c, Whi + (size_t)(k0 + r) * Dd + n0 + c);
            cp16(Bl + r * BLD + c, Wlo + (size_t)(k0 + r) * Dd + n0 + c);
        }
        cp_commit();
    };

    load_stage(0, 0);

    const int KT = Dd / BK;   // 32
    for (int kt = 0; kt < KT; kt++) {
        int s = kt & 1;
        if (kt + 1 < KT) { load_stage(s ^ 1, (kt + 1) * BK); cp_wait<1>(); }
        else             { cp_wait<0>(); }
        __syncthreads();

        bf16* Ah = S + s * GSTG;
        bf16* Al = Ah + 5120;
        bf16* Bh = Al + 5120;
        bf16* Bl = Bh + 4352;
        #pragma unroll
        for (int ks = 0; ks < BK; ks += 16) {
            wmma::fragment<wmma::matrix_b, 16, 16, 16, bf16, wmma::row_major> bfh[2], bfl[2];
            #pragma unroll
            for (int j = 0; j < 2; j++) {
                wmma::load_matrix_sync(bfh[j], &Bh[ks * BLD + wn * 32 + j * 16], BLD);
                wmma::load_matrix_sync(bfl[j], &Bl[ks * BLD + wn * 32 + j * 16], BLD);
            }
            #pragma unroll
            for (int i = 0; i < 4; i++) {
                wmma::fragment<wmma::matrix_a, 16, 16, 16, bf16, wmma::row_major> ah, al;
                wmma::load_matrix_sync(ah, &Ah[(wm * 64 + i * 16) * ALD + ks], ALD);
                wmma::load_matrix_sync(al, &Al[(wm * 64 + i * 16) * ALD + ks], ALD);
                #pragma unroll
                for (int j = 0; j < 2; j++) {
                    wmma::mma_sync(acc[i][j], ah, bfh[j], acc[i][j]);
                    wmma::mma_sync(acc[i][j], ah, bfl[j], acc[i][j]);
                    wmma::mma_sync(acc[i][j], al, bfh[j], acc[i][j]);
                }
            }
        }
        __syncthreads();
    }

    // Epilogue: stage fp32 tile in smem, then bias/acc/split/store
    float* st = reinterpret_cast<float*>(smraw);   // 128 x 136 fp32
    #pragma unroll
    for (int i = 0; i < 4; i++)
        #pragma unroll
        for (int j = 0; j < 2; j++)
            wmma::store_matrix_sync(&st[(wm * 64 + i * 16) * BLD + wn * 32 + j * 16],
                                    acc[i][j], BLD, wmma::mem_row_major);
    __syncthreads();

    const int row = tid >> 1;
    const int cb = (tid & 1) * 64;
    #pragma unroll
    for (int q = 0; q < 8; q++) {
        int col = cb + q * 8;
        float4 v0 = *reinterpret_cast<float4*>(&st[row * BLD + col]);
        float4 v1 = *reinterpret_cast<float4*>(&st[row * BLD + col + 4]);
        float4 b0 = *reinterpret_cast<const float4*>(&bias[n0 + col]);
        float4 b1 = *reinterpret_cast<const float4*>(&bias[n0 + col + 4]);
        v0.x += b0.x; v0.y += b0.y; v0.z += b0.z; v0.w += b0.w;
        v1.x += b1.x; v1.y += b1.y; v1.z += b1.z; v1.w += b1.w;
        size_t go = (size_t)(m0 + row) * Dd + n0 + col;
        if (ACC) {
            float4 o0 = *reinterpret_cast<const float4*>(&Cf[go]);
            float4 o1 = *reinterpret_cast<const float4*>(&Cf[go + 4]);
            v0.x += o0.x; v0.y += o0.y; v0.z += o0.z; v0.w += o0.w;
            v1.x += o1.x; v1.y += o1.y; v1.z += o1.z; v1.w += o1.w;
        }
        if (WF32) {
            *reinterpret_cast<float4*>(&Cf[go])     = v0;
            *reinterpret_cast<float4*>(&Cf[go + 4]) = v1;
        }
        bf162 hh[4], ll[4];
        split2(v0.x, v0.y, &hh[0], &ll[0]);
        split2(v0.z, v0.w, &hh[1], &ll[1]);
        split2(v1.x, v1.y, &hh[2], &ll[2]);
        split2(v1.z, v1.w, &hh[3], &ll[3]);
        *reinterpret_cast<float4*>(&Chi[go]) = *reinterpret_cast<float4*>(hh);
        *reinterpret_cast<float4*>(&Clo[go]) = *reinterpret_cast<float4*>(ll);
    }
}

// ---------------------------------------------------------------------------
// Fused minicolumn kernel, bf16 split inputs (pre-gathered weights),
// cp.async double-buffered; epilogue writes split(mc) to act pair.
// ---------------------------------------------------------------------------
#define FSTG 19456   // elems per stage: 2*5120 + 4*2304
#define FSMEM (2 * FSTG * 2)   // bytes = 77824

__global__ __launch_bounds__(256, 2)
void fused_mc_bf(const bf16* __restrict__ Ahi, const bf16* __restrict__ Alo,
                 const bf16* __restrict__ Weh, const bf16* __restrict__ Wel,
                 const bf16* __restrict__ Wih, const bf16* __restrict__ Wil,
                 const float* __restrict__ be_l, const float* __restrict__ bi_l,
                 const float* __restrict__ Wl_l, const float* __restrict__ bl_l,
                 bf16* __restrict__ Mhi, bf16* __restrict__ Mlo) {
    extern __shared__ char smraw[];
    bf16* S = reinterpret_cast<bf16*>(smraw);

    const int m0 = blockIdx.y * BM;
    const int n0 = blockIdx.x * FN;
    const int tid = threadIdx.x;
    const int wid = tid >> 5;
    const int wm = wid >> 2;   // 0..1
    const int wn = wid & 3;    // 0..3 (16-col band)

    wmma::fragment<wmma::accumulator, 16, 16, 16, float> acc_e[4], acc_i[4];
    #pragma unroll
    for (int i = 0; i < 4; i++) {
        wmma::fill_fragment(acc_e[i], 0.0f);
        wmma::fill_fragment(acc_i[i], 0.0f);
    }

    auto load_stage = [&](int s, int k0) {
        bf16* Ah = S + s * FSTG;
        bf16* Al = Ah + 5120;
        bf16* Eh = Al + 5120;
        bf16* El = Eh + 2304;
        bf16* Ih = El + 2304;
        bf16* Il = Ih + 2304;
        #pragma unroll
        for (int it = 0; it < 2; it++) {
            int item = tid + it * 256;
            int r = item >> 2, c = (item & 3) * 8;
            cp16(Ah + r * ALD + c, Ahi + (size_t)(m0 + r) * Dd + k0 + c);
            cp16(Al + r * ALD + c, Alo + (size_t)(m0 + r) * Dd + k0 + c);
        }
        {
            int r = tid >> 3, c = (tid & 7) * 8;
            size_t go = (size_t)(k0 + r) * Dd + n0 + c;
            int so = r * FBLD + c;
            cp16(Eh + so, Weh + go);
            cp16(El + so, Wel + go);
            cp16(Ih + so, Wih + go);
            cp16(Il + so, Wil + go);
        }
        cp_commit();
    };

    load_stage(0, 0);

    const int KT = Dd / BK;
    for (int kt = 0; kt < KT; kt++) {
        int s = kt & 1;
        if (kt + 1 < KT) { load_stage(s ^ 1, (kt + 1) * BK); cp_wait<1>(); }
        else             { cp_wait<0>(); }
        __syncthreads();

        bf16* Ah = S + s * FSTG;
        bf16* Al = Ah + 5120;
        bf16* Eh = Al + 5120;
        bf16* El = Eh + 2304;
        bf16* Ih = El + 2304;
        bf16* Il = Ih + 2304;
        #pragma unroll
        for (int ks = 0; ks < BK; ks += 16) {
            wmma::fragment<wmma::matrix_b, 16, 16, 16, bf16, wmma::row_major> beh, bel, bih, bil;
            wmma::load_matrix_sync(beh, &Eh[ks * FBLD + wn * 16], FBLD);
            wmma::load_matrix_sync(bel, &El[ks * FBLD + wn * 16], FBLD);
            wmma::load_matrix_sync(bih, &Ih[ks * FBLD + wn * 16], FBLD);
            wmma::load_matrix_sync(bil, &Il[ks * FBLD + wn * 16], FBLD);
            #pragma unroll
            for (int i = 0; i < 4; i++) {
                wmma::fragment<wmma::matrix_a, 16, 16, 16, bf16, wmma::row_major> ah, al;
                wmma::load_matrix_sync(ah, &Ah[(wm * 64 + i * 16) * ALD + ks], ALD);
                wmma::load_matrix_sync(al, &Al[(wm * 64 + i * 16) * ALD + ks], ALD);
                wmma::mma_sync(acc_e[i], ah, beh, acc_e[i]);
                wmma::mma_sync(acc_e[i], ah, bel, acc_e[i]);
                wmma::mma_sync(acc_e[i], al, beh, acc_e[i]);
                wmma::mma_sync(acc_i[i], ah, bih, acc_i[i]);
                wmma::mma_sync(acc_i[i], ah, bil, acc_i[i]);
                wmma::mma_sync(acc_i[i], al, bih, acc_i[i]);
            }
        }
        __syncthreads();
    }

    // Epilogue staging (aliases stage buffers): exc/inh fp32 + Wl
    float* exc_s = reinterpret_cast<float*>(smraw);        // 128*72
    float* inh_s = exc_s + BM * FBLD;                      // 128*72
    float* wl_s  = inh_s + BM * FBLD;                      // 1024
    #pragma unroll
    for (int i = 0; i < 4; i++) {
        wmma::store_matrix_sync(&exc_s[(wm * 64 + i * 16) * FBLD + wn * 16],
                                acc_e[i], FBLD, wmma::mem_row_major);
        wmma::store_matrix_sync(&inh_s[(wm * 64 + i * 16) * FBLD + wn * 16],
                                acc_i[i], FBLD, wmma::mem_row_major);
    }
    *reinterpret_cast<float4*>(&wl_s[tid * 4]) =
        *reinterpret_cast<const float4*>(&Wl_l[(size_t)n0 * Hh + tid * 4]);
    __syncthreads();

    const int b = tid >> 1;
    #pragma unroll
    for (int mcq = 0; mcq < 2; mcq++) {
        int ml = (tid & 1) * 2 + mcq;      // local minicolumn 0..3
        float ihv[16];
        #pragma unroll
        for (int h = 0; h < 16; h++)
            ihv[h] = fmaxf(inh_s[b * FBLD + ml * 16 + h] + bi_l[n0 + ml * 16 + h], 0.0f);
        #pragma unroll
        for (int kq = 0; kq < 4; kq++) {
            float r[4];
            #pragma unroll
            for (int e = 0; e < 4; e++) {
                int k = kq * 4 + e;
                int col = n0 + ml * 16 + k;
                float lat = bl_l[col];
                #pragma unroll
                for (int h = 0; h < 16; h++)
                    lat += ihv[h] * wl_s[ml * 256 + h * 16 + k];
                float ex = fmaxf(exc_s[b * FBLD + ml * 16 + k] + be_l[col], 0.0f);
                r[e] = fmaxf(ex - lat, 0.0f);
            }
            bf162 h0, h1, l0, l1;
            split2(r[0], r[1], &h0, &l0);
            split2(r[2], r[3], &h1, &l1);
            size_t go = (size_t)(m0 + b) * Dd + n0 + ml * 16 + kq * 4;
            *reinterpret_cast<bf162*>(&Mhi[go])     = h0;
            *reinterpret_cast<bf162*>(&Mhi[go + 2]) = h1;
            *reinterpret_cast<bf162*>(&Mlo[go])     = l0;
            *reinterpret_cast<bf162*>(&Mlo[go + 2]) = l1;
        }
    }
}

// ---------------------------------------------------------------------------
// Host orchestration
// ---------------------------------------------------------------------------
extern "C" void kernel_launch(void* const* d_in, const int* in_sizes, int n_in,
                              void* d_out, int out_size) {
    const float* x    = (const float*)d_in[0];
    const float* We   = (const float*)d_in[1];
    const float* be   = (const float*)d_in[2];
    const float* Wi   = (const float*)d_in[3];
    const float* bi   = (const float*)d_in[4];
    const float* Wl   = (const float*)d_in[5];
    const float* bl   = (const float*)d_in[6];
    const float* Wlat = (const float*)d_in[7];
    const float* blat = (const float*)d_in[8];
    const float* Wv   = (const float*)d_in[9];
    const float* bv   = (const float*)d_in[10];
    const float* Wo   = (const float*)d_in[11];
    const float* bo   = (const float*)d_in[12];
    const float* fbW  = (const float*)d_in[13];
    const float* fbb  = (const float*)d_in[14];
    float* out = (float*)d_out;

    bf16 *wlat_h, *wlat_l, *wv_h, *wv_l, *wo_h, *wo_l, *fb_h, *fb_l;
    bf16 *we_h, *we_l, *wi_h, *wi_l, *a0h, *a0l, *a1h, *a1l;
    cudaGetSymbolAddress((void**)&wlat_h, g_wlat_h);
    cudaGetSymbolAddress((void**)&wlat_l, g_wlat_l);
    cudaGetSymbolAddress((void**)&wv_h,   g_wv_h);
    cudaGetSymbolAddress((void**)&wv_l,   g_wv_l);
    cudaGetSymbolAddress((void**)&wo_h,   g_wo_h);
    cudaGetSymbolAddress((void**)&wo_l,   g_wo_l);
    cudaGetSymbolAddress((void**)&fb_h,   g_fb_h);
    cudaGetSymbolAddress((void**)&fb_l,   g_fb_l);
    cudaGetSymbolAddress((void**)&we_h,   g_we_h);
    cudaGetSymbolAddress((void**)&we_l,   g_we_l);
    cudaGetSymbolAddress((void**)&wi_h,   g_wi_h);
    cudaGetSymbolAddress((void**)&wi_l,   g_wi_l);
    cudaGetSymbolAddress((void**)&a0h,    g_a0h);
    cudaGetSymbolAddress((void**)&a0l,    g_a0l);
    cudaGetSymbolAddress((void**)&a1h,    g_a1h);
    cudaGetSymbolAddress((void**)&a1l,    g_a1l);

    cudaFuncSetAttribute(gemm_bf<false, false>, cudaFuncAttributeMaxDynamicSharedMemorySize, GSMEM);
    cudaFuncSetAttribute(gemm_bf<false, true>,  cudaFuncAttributeMaxDynamicSharedMemorySize, GSMEM);
    cudaFuncSetAttribute(gemm_bf<true, true>,   cudaFuncAttributeMaxDynamicSharedMemorySize, GSMEM);
    cudaFuncSetAttribute(fused_mc_bf,           cudaFuncAttributeMaxDynamicSharedMemorySize, FSMEM);

    // --- Preconversion (inside graph; cheap) ---
    conv_mat<<<6 * M1 / 4 / 256, 256>>>(Wlat, wlat_h, wlat_l);
    conv_mat<<<6 * M1 / 4 / 256, 256>>>(Wv,   wv_h,   wv_l);
    conv_mat<<<6 * M1 / 4 / 256, 256>>>(Wo,   wo_h,   wo_l);
    conv_mat<<<5 * M1 / 4 / 256, 256>>>(fbW,  fb_h,   fb_l);
    conv_gather<<<dim3(M1 / 4 / 256, 6), 256>>>(We, we_h, we_l);
    conv_gather<<<dim3(M1 / 4 / 256, 6), 256>>>(Wi, wi_h, wi_l);
    conv_mat<<<(int)(BD / 4 / 256), 256>>>(x, a1h, a1l);   // carry = pair1

    const size_t WL_STRIDE = (size_t)NMC * Hh * Hh;
    dim3 gridF(Dd / FN, Bsz / BM);    // 16 x 128
    dim3 gridG(Dd / BN, Bsz / BM);    // 8 x 128

    for (int l = 0; l < Lc; l++) {
        fused_mc_bf<<<gridF, 256, FSMEM>>>(a1h, a1l,
            we_h + (size_t)l * M1, we_l + (size_t)l * M1,
            wi_h + (size_t)l * M1, wi_l + (size_t)l * M1,
            be + l * Dd, bi + l * Dd, Wl + l * WL_STRIDE, bl + l * Dd,
            a0h, a0l);
        gemm_bf<false, false><<<gridG, 256, GSMEM>>>(a0h, a0l,
            wlat_h + (size_t)l * M1, wlat_l + (size_t)l * M1,
            blat + l * Dd, nullptr, a1h, a1l);
        gemm_bf<false, false><<<gridG, 256, GSMEM>>>(a1h, a1l,
            wv_h + (size_t)l * M1, wv_l + (size_t)l * M1,
            bv + l * Dd, nullptr, a0h, a0l);
        gemm_bf<false, true><<<gridG, 256, GSMEM>>>(a0h, a0l,
            wo_h + (size_t)l * M1, wo_l + (size_t)l * M1,
            bo + l * Dd, out + (size_t)l * BD, a1h, a1l);
        // carry for next layer = pair1 (just written)
    }

    // Feedback chain: fb_in starts at pair1 (= out[5] split)
    int p = 1;
    for (int i = 0; i < Lc - 1; i++) {
        int idx = Lc - 2 - i;
        bf16* sh = p ? a1h : a0h;
        bf16* sl = p ? a1l : a0l;
        bf16* dh = p ? a0h : a1h;
        bf16* dl = p ? a0l : a1l;
        gemm_bf<true, true><<<gridG, 256, GSMEM>>>(sh, sl,
            fb_h + (size_t)i * M1, fb_l + (size_t)i * M1,
            fbb + i * Dd, out + (size_t)idx * BD, dh, dl);
        p ^= 1;
    }
}

// round 5
// speedup vs baseline: 2.6602x; 1.1767x over previous
#include <cuda_runtime.h>
#include <cuda_bf16.h>
#include <mma.h>
#include <cstdint>

using namespace nvcuda;
typedef __nv_bfloat16  bf16;
typedef __nv_bfloat162 bf162;

// Problem constants
#define Bsz 16384
#define Dd  1024
#define Lc  6
#define NMC 64
#define Hh  16
#define M1  (1024 * 1024)
#define BD  ((size_t)Bsz * Dd)

// Tiling: block 128x128 (generic) / 128x64 (fused), 4 warps, warp 64x64 / 64x32(x2)
#define BK   32
#define LDK  40                       // padded k-stride (elems) for smem tiles
#define MATB (128 * LDK * 2)          // bytes per smem matrix (128 rows x 40 bf16)
#define GSTGB (4 * MATB)              // Ah Al Bh Bl = 40960
#define FSTGB (2 * MATB + 4 * (64 * LDK * 2))  // Ah Al + 4x(64x40) = 40960
#define GDSM (2 * GSTGB)              // 81920
#define FDSM (2 * FSTGB)              // 81920
#define NKT  (Dd / BK)                // 32

// ---------------------------------------------------------------------------
// Persistent bf16 split buffers. Weights stored transposed: [n][k] k-major.
// ---------------------------------------------------------------------------
__device__ bf16 g_wlat_h[6 * M1], g_wlat_l[6 * M1];
__device__ bf16 g_wv_h  [6 * M1], g_wv_l  [6 * M1];
__device__ bf16 g_wo_h  [6 * M1], g_wo_l  [6 * M1];
__device__ bf16 g_fb_h  [5 * M1], g_fb_l  [5 * M1];
__device__ bf16 g_we_h  [6 * M1], g_we_l  [6 * M1];   // [n=m*16+h][k=d]
__device__ bf16 g_wi_h  [6 * M1], g_wi_l  [6 * M1];
__device__ bf16 g_a0h[BD], g_a0l[BD], g_a1h[BD], g_a1l[BD];

__device__ __forceinline__ void split1(float v, bf16* h, bf16* l) {
    bf16 hh = __float2bfloat16(v);
    *h = hh;
    *l = __float2bfloat16(v - __bfloat162float(hh));
}

__device__ __forceinline__ void cp16(void* smem, const void* g) {
    uint32_t s = (uint32_t)__cvta_generic_to_shared(smem);
    asm volatile("cp.async.cg.shared.global [%0], [%1], 16;" :: "r"(s), "l"(g));
}
__device__ __forceinline__ void cp_commit() { asm volatile("cp.async.commit_group;"); }
template <int N>
__device__ __forceinline__ void cp_wait() {
    asm volatile("cp.async.wait_group %0;" :: "n"(N));
}

// ---------------------------------------------------------------------------
// Conversion kernels (one-time per launch)
// ---------------------------------------------------------------------------
__global__ void conv_T(const float* __restrict__ src, bf16* __restrict__ hi,
                       bf16* __restrict__ lo) {
    __shared__ float t[32][33];
    const int l = blockIdx.z;
    const int k0 = blockIdx.y * 32, n0 = blockIdx.x * 32;
    const float* S = src + (size_t)l * M1;
    const int r = threadIdx.x >> 5, c = threadIdx.x & 31;
    #pragma unroll
    for (int i = 0; i < 4; i++)
        t[r + i * 8][c] = S[(size_t)(k0 + r + i * 8) * Dd + n0 + c];
    __syncthreads();
    bf16* H = hi + (size_t)l * M1;
    bf16* L = lo + (size_t)l * M1;
    #pragma unroll
    for (int i = 0; i < 4; i++) {
        bf16 hb, lb; split1(t[c][r + i * 8], &hb, &lb);
        size_t o = (size_t)(n0 + r + i * 8) * Dd + k0 + c;
        H[o] = hb; L[o] = lb;
    }
}

// out[l][m*16+h][d] = src[l][m][d][h]
__global__ void conv_gT(const float* __restrict__ src, bf16* __restrict__ hi,
                        bf16* __restrict__ lo) {
    __shared__ float t[64][17];
    const int d0 = blockIdx.x * 64, m = blockIdx.y, l = blockIdx.z;
    const int tid = threadIdx.x;
    {
        int dd = tid >> 2, h4 = (tid & 3) * 4;
        float4 v = *reinterpret_cast<const float4*>(
            &src[((size_t)(l * NMC + m) * Dd + d0 + dd) * Hh + h4]);
        t[dd][h4] = v.x; t[dd][h4 + 1] = v.y; t[dd][h4 + 2] = v.z; t[dd][h4 + 3] = v.w;
    }
    __syncthreads();
    int h = tid >> 4, cq = tid & 15;
    size_t rowo = (size_t)l * M1 + (size_t)(m * 16 + h) * Dd + d0 + cq * 4;
    #pragma unroll
    for (int j = 0; j < 4; j++) {
        bf16 hb, lb; split1(t[cq * 4 + j][h], &hb, &lb);
        hi[rowo + j] = hb; lo[rowo + j] = lb;
    }
}

__global__ void conv_act(const float* __restrict__ src, bf16* __restrict__ hi,
                         bf16* __restrict__ lo) {
    size_t i = ((size_t)blockIdx.x * blockDim.x + threadIdx.x) * 4;
    float4 v = *reinterpret_cast<const float4*>(src + i);
    bf16 hs[4], ls[4];
    split1(v.x, &hs[0], &ls[0]); split1(v.y, &hs[1], &ls[1]);
    split1(v.z, &hs[2], &ls[2]); split1(v.w, &hs[3], &ls[3]);
    *reinterpret_cast<float2*>(hi + i) = *reinterpret_cast<float2*>(hs);
    *reinterpret_cast<float2*>(lo + i) = *reinterpret_cast<float2*>(ls);
}

// ---------------------------------------------------------------------------
// Generic GEMM: C = (ACC ? Cf : 0) + A @ W + bias. Warp tile 64x64.
// A split [Bsz][Dd] row-major; WT split [Dd(n)][Dd(k)] k-major.
// ---------------------------------------------------------------------------
template <bool ACC, bool WF32>
__global__ __launch_bounds__(128, 2)
void gemm_w(const bf16* __restrict__ Ahi, const bf16* __restrict__ Alo,
            const bf16* __restrict__ Whi, const bf16* __restrict__ Wlo,
            const float* __restrict__ bias, float* __restrict__ Cf,
            bf16* __restrict__ Chi, bf16* __restrict__ Clo) {
    extern __shared__ char smraw[];
    const int tid = threadIdx.x, wid = tid >> 5, lane = tid & 31;
    const int wm = wid >> 1, wn = wid & 1;
    const int m0 = blockIdx.y * 128, n0 = blockIdx.x * 128;

    wmma::fragment<wmma::accumulator, 16, 16, 16, float> acc[4][4];
    #pragma unroll
    for (int i = 0; i < 4; i++)
        #pragma unroll
        for (int j = 0; j < 4; j++)
            wmma::fill_fragment(acc[i][j], 0.0f);

    auto load_stage = [&](int st, int kt) {
        bf16* Ah = reinterpret_cast<bf16*>(smraw + st * GSTGB);
        bf16* Al = Ah + 128 * LDK;
        bf16* Bh = Al + 128 * LDK;
        bf16* Bl = Bh + 128 * LDK;
        const int k0 = kt * BK;
        #pragma unroll
        for (int t = 0; t < 4; t++) {
            int item = tid + t * 128;
            int r = item >> 2, c = (item & 3) * 8;
            size_t ga = (size_t)(m0 + r) * Dd + k0 + c;
            size_t gb = (size_t)(n0 + r) * Dd + k0 + c;
            cp16(Ah + r * LDK + c, Ahi + ga);
            cp16(Al + r * LDK + c, Alo + ga);
            cp16(Bh + r * LDK + c, Whi + gb);
            cp16(Bl + r * LDK + c, Wlo + gb);
        }
        cp_commit();
    };

    load_stage(0, 0);
    for (int kt = 0; kt < NKT; kt++) {
        int st = kt & 1;
        if (kt + 1 < NKT) { load_stage(st ^ 1, kt + 1); cp_wait<1>(); }
        else              { cp_wait<0>(); }
        __syncthreads();

        bf16* Ah = reinterpret_cast<bf16*>(smraw + st * GSTGB);
        bf16* Al = Ah + 128 * LDK;
        bf16* Bh = Al + 128 * LDK;
        bf16* Bl = Bh + 128 * LDK;
        #pragma unroll
        for (int ks = 0; ks < BK; ks += 16) {
            wmma::fragment<wmma::matrix_b, 16, 16, 16, bf16, wmma::col_major> bh[4], bl[4];
            #pragma unroll
            for (int j = 0; j < 4; j++) {
                wmma::load_matrix_sync(bh[j], &Bh[(wn * 64 + j * 16) * LDK + ks], LDK);
                wmma::load_matrix_sync(bl[j], &Bl[(wn * 64 + j * 16) * LDK + ks], LDK);
            }
            #pragma unroll
            for (int i = 0; i < 4; i++) {
                wmma::fragment<wmma::matrix_a, 16, 16, 16, bf16, wmma::row_major> ah, al;
                wmma::load_matrix_sync(ah, &Ah[(wm * 64 + i * 16) * LDK + ks], LDK);
                wmma::load_matrix_sync(al, &Al[(wm * 64 + i * 16) * LDK + ks], LDK);
                #pragma unroll
                for (int j = 0; j < 4; j++) {
                    wmma::mma_sync(acc[i][j], ah, bh[j], acc[i][j]);
                    wmma::mma_sync(acc[i][j], ah, bl[j], acc[i][j]);
                    wmma::mma_sync(acc[i][j], al, bh[j], acc[i][j]);
                }
            }
        }
        __syncthreads();
    }

    __syncthreads();
    // Epilogue: per-warp private 16x20 patch
    float* patch = reinterpret_cast<float*>(smraw) + wid * 16 * 20;
    const int er = lane >> 1, eh = (lane & 1) * 8;
    #pragma unroll
    for (int i = 0; i < 4; i++) {
        #pragma unroll
        for (int j = 0; j < 4; j++) {
            wmma::store_matrix_sync(patch, acc[i][j], 20, wmma::mem_row_major);
            __syncwarp();
            int gr = m0 + wm * 64 + i * 16 + er;
            int gc = n0 + wn * 64 + j * 16 + eh;
            size_t go = (size_t)gr * Dd + gc;
            float4 b0 = *reinterpret_cast<const float4*>(&bias[gc]);
            float4 b1 = *reinterpret_cast<const float4*>(&bias[gc + 4]);
            float v[8];
            #pragma unroll
            for (int e = 0; e < 8; e++) v[e] = patch[er * 20 + eh + e];
            v[0] += b0.x; v[1] += b0.y; v[2] += b0.z; v[3] += b0.w;
            v[4] += b1.x; v[5] += b1.y; v[6] += b1.z; v[7] += b1.w;
            if (ACC) {
                float4 o0 = *reinterpret_cast<const float4*>(&Cf[go]);
                float4 o1 = *reinterpret_cast<const float4*>(&Cf[go + 4]);
                v[0] += o0.x; v[1] += o0.y; v[2] += o0.z; v[3] += o0.w;
                v[4] += o1.x; v[5] += o1.y; v[6] += o1.z; v[7] += o1.w;
            }
            if (WF32) {
                *reinterpret_cast<float4*>(&Cf[go])     = *reinterpret_cast<float4*>(&v[0]);
                *reinterpret_cast<float4*>(&Cf[go + 4]) = *reinterpret_cast<float4*>(&v[4]);
            }
            bf16 hs[8], ls[8];
            #pragma unroll
            for (int e = 0; e < 8; e++) split1(v[e], &hs[e], &ls[e]);
            *reinterpret_cast<float4*>(&Chi[go]) = *reinterpret_cast<float4*>(hs);
            *reinterpret_cast<float4*>(&Clo[go]) = *reinterpret_cast<float4*>(ls);
            __syncwarp();
        }
    }
}

// ---------------------------------------------------------------------------
// Fused minicolumn kernel: block 128x64 (4 minicolumns), warp 64x32 for e and i.
// ---------------------------------------------------------------------------
__global__ __launch_bounds__(128, 2)
void fused_w(const bf16* __restrict__ Ahi, const bf16* __restrict__ Alo,
             const bf16* __restrict__ Weh, const bf16* __restrict__ Wel,
             const bf16* __restrict__ Wih, const bf16* __restrict__ Wil,
             const float* __restrict__ be_l, const float* __restrict__ bi_l,
             const float* __restrict__ Wl_l, const float* __restrict__ bl_l,
             bf16* __restrict__ Mhi, bf16* __restrict__ Mlo) {
    extern __shared__ char smraw[];
    __shared__ float swl[1024];
    __shared__ float sbe[64], sbi[64], sbl[64];

    const int tid = threadIdx.x, wid = tid >> 5, lane = tid & 31;
    const int wm = wid >> 1, wn = wid & 1;
    const int m0 = blockIdx.y * 128, n0 = blockIdx.x * 64;

    for (int i = tid; i < 256; i += 128)
        *reinterpret_cast<float4*>(&swl[i * 4]) =
            *reinterpret_cast<const float4*>(&Wl_l[(size_t)n0 * Hh + i * 4]);
    if (tid < 64) {
        sbe[tid] = be_l[n0 + tid];
        sbi[tid] = bi_l[n0 + tid];
        sbl[tid] = bl_l[n0 + tid];
    }

    wmma::fragment<wmma::accumulator, 16, 16, 16, float> ae[4][2], ai[4][2];
    #pragma unroll
    for (int i = 0; i < 4; i++)
        #pragma unroll
        for (int j = 0; j < 2; j++) {
            wmma::fill_fragment(ae[i][j], 0.0f);
            wmma::fill_fragment(ai[i][j], 0.0f);
        }

    auto load_stage = [&](int st, int kt) {
        bf16* Ah = reinterpret_cast<bf16*>(smraw + st * FSTGB);
        bf16* Al = Ah + 128 * LDK;
        bf16* Eh = Al + 128 * LDK;
        bf16* El = Eh + 64 * LDK;
        bf16* Ih = El + 64 * LDK;
        bf16* Il = Ih + 64 * LDK;
        const int k0 = kt * BK;
        #pragma unroll
        for (int t = 0; t < 4; t++) {
            int item = tid + t * 128;
            int r = item >> 2, c = (item & 3) * 8;
            size_t ga = (size_t)(m0 + r) * Dd + k0 + c;
            cp16(Ah + r * LDK + c, Ahi + ga);
            cp16(Al + r * LDK + c, Alo + ga);
        }
        #pragma unroll
        for (int t = 0; t < 2; t++) {
            int item = tid + t * 128;
            int r = item >> 2, c = (item & 3) * 8;
            size_t gb = (size_t)(n0 + r) * Dd + k0 + c;
            cp16(Eh + r * LDK + c, Weh + gb);
            cp16(El + r * LDK + c, Wel + gb);
            cp16(Ih + r * LDK + c, Wih + gb);
            cp16(Il + r * LDK + c, Wil + gb);
        }
        cp_commit();
    };

    load_stage(0, 0);
    for (int kt = 0; kt < NKT; kt++) {
        int st = kt & 1;
        if (kt + 1 < NKT) { load_stage(st ^ 1, kt + 1); cp_wait<1>(); }
        else              { cp_wait<0>(); }
        __syncthreads();

        bf16* Ah = reinterpret_cast<bf16*>(smraw + st * FSTGB);
        bf16* Al = Ah + 128 * LDK;
        bf16* Eh = Al + 128 * LDK;
        bf16* El = Eh + 64 * LDK;
        bf16* Ih = El + 64 * LDK;
        bf16* Il = Ih + 64 * LDK;
        #pragma unroll
        for (int ks = 0; ks < BK; ks += 16) {
            wmma::fragment<wmma::matrix_b, 16, 16, 16, bf16, wmma::col_major>
                eh[2], el[2], ih[2], il[2];
            #pragma unroll
            for (int j = 0; j < 2; j++) {
                int nb = (wn * 32 + j * 16) * LDK + ks;
                wmma::load_matrix_sync(eh[j], &Eh[nb], LDK);
                wmma::load_matrix_sync(el[j], &El[nb], LDK);
                wmma::load_matrix_sync(ih[j], &Ih[nb], LDK);
                wmma::load_matrix_sync(il[j], &Il[nb], LDK);
            }
            #pragma unroll
            for (int i = 0; i < 4; i++) {
                wmma::fragment<wmma::matrix_a, 16, 16, 16, bf16, wmma::row_major> ah, al;
                wmma::load_matrix_sync(ah, &Ah[(wm * 64 + i * 16) * LDK + ks], LDK);
                wmma::load_matrix_sync(al, &Al[(wm * 64 + i * 16) * LDK + ks], LDK);
                #pragma unroll
                for (int j = 0; j < 2; j++) {
                    wmma::mma_sync(ae[i][j], ah, eh[j], ae[i][j]);
                    wmma::mma_sync(ae[i][j], ah, el[j], ae[i][j]);
                    wmma::mma_sync(ae[i][j], al, eh[j], ae[i][j]);
                    wmma::mma_sync(ai[i][j], ah, ih[j], ai[i][j]);
                    wmma::mma_sync(ai[i][j], ah, il[j], ai[i][j]);
                    wmma::mma_sync(ai[i][j], al, ih[j], ai[i][j]);
                }
            }
        }
        __syncthreads();
    }

    __syncthreads();
    // Epilogue: per-warp patches for exc and inh; lateral inhibition per minicolumn
    float* pe = reinterpret_cast<float*>(smraw) + wid * 2 * 16 * 20;
    float* pi = pe + 16 * 20;
    const int er = lane >> 1, eh8 = (lane & 1) * 8;
    #pragma unroll
    for (int i = 0; i < 4; i++) {
        #pragma unroll
        for (int j = 0; j < 2; j++) {
            wmma::store_matrix_sync(pe, ae[i][j], 20, wmma::mem_row_major);
            wmma::store_matrix_sync(pi, ai[i][j], 20, wmma::mem_row_major);
            __syncwarp();
            int ml = wn * 2 + j;                // local minicolumn 0..3
            int gr = m0 + wm * 64 + i * 16 + er;
            float ihv[16];
            #pragma unroll
            for (int h = 0; h < 16; h++)
                ihv[h] = fmaxf(pi[er * 20 + h] + sbi[ml * 16 + h], 0.0f);
            bf16 hs[8], ls[8];
            #pragma unroll
            for (int e = 0; e < 8; e++) {
                int k = eh8 + e;
                float lat = sbl[ml * 16 + k];
                #pragma unroll
                for (int h = 0; h < 16; h++)
                    lat += ihv[h] * swl[ml * 256 + h * 16 + k];
                float ex = fmaxf(pe[er * 20 + k] + sbe[ml * 16 + k], 0.0f);
                split1(fmaxf(ex - lat, 0.0f), &hs[e], &ls[e]);
            }
            size_t go = (size_t)gr * Dd + n0 + ml * 16 + eh8;
            *reinterpret_cast<float4*>(&Mhi[go]) = *reinterpret_cast<float4*>(hs);
            *reinterpret_cast<float4*>(&Mlo[go]) = *reinterpret_cast<float4*>(ls);
            __syncwarp();
        }
    }
}

// ---------------------------------------------------------------------------
// Host orchestration
// ---------------------------------------------------------------------------
extern "C" void kernel_launch(void* const* d_in, const int* in_sizes, int n_in,
                              void* d_out, int out_size) {
    const float* x    = (const float*)d_in[0];
    const float* We   = (const float*)d_in[1];
    const float* be   = (const float*)d_in[2];
    const float* Wi   = (const float*)d_in[3];
    const float* bi   = (const float*)d_in[4];
    const float* Wl   = (const float*)d_in[5];
    const float* bl   = (const float*)d_in[6];
    const float* Wlat = (const float*)d_in[7];
    const float* blat = (const float*)d_in[8];
    const float* Wv   = (const float*)d_in[9];
    const float* bv   = (const float*)d_in[10];
    const float* Wo   = (const float*)d_in[11];
    const float* bo   = (const float*)d_in[12];
    const float* fbW  = (const float*)d_in[13];
    const float* fbb  = (const float*)d_in[14];
    float* out = (float*)d_out;

    bf16 *wlat_h, *wlat_l, *wv_h, *wv_l, *wo_h, *wo_l, *fb_h, *fb_l;
    bf16 *we_h, *we_l, *wi_h, *wi_l, *a0h, *a0l, *a1h, *a1l;
    cudaGetSymbolAddress((void**)&wlat_h, g_wlat_h);
    cudaGetSymbolAddress((void**)&wlat_l, g_wlat_l);
    cudaGetSymbolAddress((void**)&wv_h,   g_wv_h);
    cudaGetSymbolAddress((void**)&wv_l,   g_wv_l);
    cudaGetSymbolAddress((void**)&wo_h,   g_wo_h);
    cudaGetSymbolAddress((void**)&wo_l,   g_wo_l);
    cudaGetSymbolAddress((void**)&fb_h,   g_fb_h);
    cudaGetSymbolAddress((void**)&fb_l,   g_fb_l);
    cudaGetSymbolAddress((void**)&we_h,   g_we_h);
    cudaGetSymbolAddress((void**)&we_l,   g_we_l);
    cudaGetSymbolAddress((void**)&wi_h,   g_wi_h);
    cudaGetSymbolAddress((void**)&wi_l,   g_wi_l);
    cudaGetSymbolAddress((void**)&a0h,    g_a0h);
    cudaGetSymbolAddress((void**)&a0l,    g_a0l);
    cudaGetSymbolAddress((void**)&a1h,    g_a1h);
    cudaGetSymbolAddress((void**)&a1l,    g_a1l);

    cudaFuncSetAttribute(gemm_w<false, false>, cudaFuncAttributeMaxDynamicSharedMemorySize, GDSM);
    cudaFuncSetAttribute(gemm_w<false, true>,  cudaFuncAttributeMaxDynamicSharedMemorySize, GDSM);
    cudaFuncSetAttribute(gemm_w<true, true>,   cudaFuncAttributeMaxDynamicSharedMemorySize, GDSM);
    cudaFuncSetAttribute(fused_w,              cudaFuncAttributeMaxDynamicSharedMemorySize, FDSM);

    // One-time conversions (weights transposed to [N][K], split hi/lo)
    conv_T<<<dim3(32, 32, 6), 256>>>(Wlat, wlat_h, wlat_l);
    conv_T<<<dim3(32, 32, 6), 256>>>(Wv,   wv_h,   wv_l);
    conv_T<<<dim3(32, 32, 6), 256>>>(Wo,   wo_h,   wo_l);
    conv_T<<<dim3(32, 32, 5), 256>>>(fbW,  fb_h,   fb_l);
    conv_gT<<<dim3(16, 64, 6), 256>>>(We, we_h, we_l);
    conv_gT<<<dim3(16, 64, 6), 256>>>(Wi, wi_h, wi_l);
    conv_act<<<(int)(BD / 4 / 256), 256>>>(x, a1h, a1l);

    const size_t WL_STRIDE = (size_t)NMC * Hh * Hh;
    dim3 gridG(Dd / 128, Bsz / 128);   // 8 x 128
    dim3 gridF(Dd / 64,  Bsz / 128);   // 16 x 128

    for (int l = 0; l < Lc; l++) {
        fused_w<<<gridF, 128, FDSM>>>(a1h, a1l,
            we_h + (size_t)l * M1, we_l + (size_t)l * M1,
            wi_h + (size_t)l * M1, wi_l + (size_t)l * M1,
            be + l * Dd, bi + l * Dd, Wl + l * WL_STRIDE, bl + l * Dd,
            a0h, a0l);
        gemm_w<false, false><<<gridG, 128, GDSM>>>(a0h, a0l,
            wlat_h + (size_t)l * M1, wlat_l + (size_t)l * M1,
            blat + l * Dd, nullptr, a1h, a1l);
        gemm_w<false, false><<<gridG, 128, GDSM>>>(a1h, a1l,
            wv_h + (size_t)l * M1, wv_l + (size_t)l * M1,
            bv + l * Dd, nullptr, a0h, a0l);
        gemm_w<false, true><<<gridG, 128, GDSM>>>(a0h, a0l,
            wo_h + (size_t)l * M1, wo_l + (size_t)l * M1,
            bo + l * Dd, out + (size_t)l * BD, a1h, a1l);
    }

    int p = 1;
    for (int i = 0; i < Lc - 1; i++) {
        int idx = Lc - 2 - i;
        bf16* sh = p ? a1h : a0h;
        bf16* sl = p ? a1l : a0l;
        bf16* dh = p ? a0h : a1h;
        bf16* dl = p ? a0l : a1l;
        gemm_w<true, true><<<gridG, 128, GDSM>>>(sh, sl,
            fb_h + (size_t)i * M1, fb_l + (size_t)i * M1,
            fbb + i * Dd, out + (size_t)idx * BD, dh, dl);
        p ^= 1;
    }
}

// round 6
// speedup vs baseline: 3.6877x; 1.3862x over previous
#include <cuda_runtime.h>
#include <cuda_bf16.h>
#include <mma.h>
#include <cstdint>

using namespace nvcuda;
typedef __nv_bfloat16  bf16;
typedef __nv_bfloat162 bf162;

// Problem constants
#define Bsz 16384
#define Dd  1024
#define Lc  6
#define NMC 64
#define Hh  16
#define M1  (1024 * 1024)
#define BD  ((size_t)Bsz * Dd)

// Tiling: block 128x128 (generic) / 128x64 (fused), 4 warps
#define BK   32
#define LDK  40
#define MATB (128 * LDK * 2)
#define GSTGB (4 * MATB)
#define FSTGB (2 * MATB + 4 * (64 * LDK * 2))
#define GDSM (2 * GSTGB)
#define FDSM (2 * FSTGB)
#define NKT  (Dd / BK)

// ---------------------------------------------------------------------------
// Persistent buffers
// ---------------------------------------------------------------------------
__device__ bf16 g_wc_h [6 * M1], g_wc_l [6 * M1];   // combo weights, [n][k]
__device__ bf16 g_wv_h [6 * M1], g_wv_l [6 * M1];   // Wv^T [n][k]
__device__ bf16 g_wo_h [6 * M1], g_wo_l [6 * M1];   // Wo^T [n][k]
__device__ bf16 g_fb_h [5 * M1], g_fb_l [5 * M1];   // fbW^T [n][k]
__device__ bf16 g_we_h [6 * M1], g_we_l [6 * M1];   // gathered [n=m*16+h][k=d]
__device__ bf16 g_wi_h [6 * M1], g_wi_l [6 * M1];
__device__ bf16 g_s1h[6 * M1], g_s1l[6 * M1];       // Wlat split row-major
__device__ bf16 g_s2h[6 * M1], g_s2l[6 * M1];       // T1 = Wlat@Wv split row-major
__device__ float g_t2[6 * M1];                      // combo fp32 row-major
__device__ float g_bc1[6 * Dd], g_bc2[6 * Dd];      // combined biases
__device__ float g_zero[Dd];                        // stays zero
__device__ bf16 g_a0h[BD], g_a0l[BD], g_a1h[BD], g_a1l[BD];

__device__ __forceinline__ void split1(float v, bf16* h, bf16* l) {
    bf16 hh = __float2bfloat16(v);
    *h = hh;
    *l = __float2bfloat16(v - __bfloat162float(hh));
}

__device__ __forceinline__ void cp16(void* smem, const void* g) {
    uint32_t s = (uint32_t)__cvta_generic_to_shared(smem);
    asm volatile("cp.async.cg.shared.global [%0], [%1], 16;" :: "r"(s), "l"(g));
}
__device__ __forceinline__ void cp_commit() { asm volatile("cp.async.commit_group;"); }
template <int N>
__device__ __forceinline__ void cp_wait() {
    asm volatile("cp.async.wait_group %0;" :: "n"(N));
}

// ---------------------------------------------------------------------------
// Conversion kernels
// ---------------------------------------------------------------------------
__global__ void conv_T(const float* __restrict__ src, bf16* __restrict__ hi,
                       bf16* __restrict__ lo) {
    __shared__ float t[32][33];
    const int l = blockIdx.z;
    const int k0 = blockIdx.y * 32, n0 = blockIdx.x * 32;
    const float* S = src + (size_t)l * M1;
    const int r = threadIdx.x >> 5, c = threadIdx.x & 31;
    #pragma unroll
    for (int i = 0; i < 4; i++)
        t[r + i * 8][c] = S[(size_t)(k0 + r + i * 8) * Dd + n0 + c];
    __syncthreads();
    bf16* H = hi + (size_t)l * M1;
    bf16* L = lo + (size_t)l * M1;
    #pragma unroll
    for (int i = 0; i < 4; i++) {
        bf16 hb, lb; split1(t[c][r + i * 8], &hb, &lb);
        size_t o = (size_t)(n0 + r + i * 8) * Dd + k0 + c;
        H[o] = hb; L[o] = lb;
    }
}

// out[l][m*16+h][d] = src[l][m][d][h]
__global__ void conv_gT(const float* __restrict__ src, bf16* __restrict__ hi,
                        bf16* __restrict__ lo) {
    __shared__ float t[64][17];
    const int d0 = blockIdx.x * 64, m = blockIdx.y, l = blockIdx.z;
    const int tid = threadIdx.x;
    {
        int dd = tid >> 2, h4 = (tid & 3) * 4;
        float4 v = *reinterpret_cast<const float4*>(
            &src[((size_t)(l * NMC + m) * Dd + d0 + dd) * Hh + h4]);
        t[dd][h4] = v.x; t[dd][h4 + 1] = v.y; t[dd][h4 + 2] = v.z; t[dd][h4 + 3] = v.w;
    }
    __syncthreads();
    int h = tid >> 4, cq = tid & 15;
    size_t rowo = (size_t)l * M1 + (size_t)(m * 16 + h) * Dd + d0 + cq * 4;
    #pragma unroll
    for (int j = 0; j < 4; j++) {
        bf16 hb, lb; split1(t[cq * 4 + j][h], &hb, &lb);
        hi[rowo + j] = hb; lo[rowo + j] = lb;
    }
}

__global__ void conv_act(const float* __restrict__ src, bf16* __restrict__ hi,
                         bf16* __restrict__ lo) {
    size_t i = ((size_t)blockIdx.x * blockDim.x + threadIdx.x) * 4;
    float4 v = *reinterpret_cast<const float4*>(src + i);
    bf16 hs[4], ls[4];
    split1(v.x, &hs[0], &ls[0]); split1(v.y, &hs[1], &ls[1]);
    split1(v.z, &hs[2], &ls[2]); split1(v.w, &hs[3], &ls[3]);
    *reinterpret_cast<float2*>(hi + i) = *reinterpret_cast<float2*>(hs);
    *reinterpret_cast<float2*>(lo + i) = *reinterpret_cast<float2*>(ls);
}

// Combined bias: bc[l][j] = sum_i bin[l][i] * W[l][i][j] + badd[l][j]
__global__ void bias_combo(const float* __restrict__ bin, const float* __restrict__ W,
                           const float* __restrict__ badd, float* __restrict__ bc) {
    const int l = blockIdx.y;
    const int j = blockIdx.x * 256 + threadIdx.x;
    const float* Wl = W + (size_t)l * M1;
    const float* bi = bin + (size_t)l * Dd;
    float s = badd[(size_t)l * Dd + j];
    for (int i = 0; i < Dd; i++) s += bi[i] * Wl[(size_t)i * Dd + j];
    bc[(size_t)l * Dd + j] = s;
}

// ---------------------------------------------------------------------------
// GEMM: C = (ACC ? Cf : 0) + A @ W + bias. Block 128x128, warp 64x64.
// z-batched via strides. WF32: write fp32 Cf. WSPLIT: write split Chi/Clo.
// ---------------------------------------------------------------------------
template <bool ACC, bool WF32, bool WSPLIT>
__global__ __launch_bounds__(128, 2)
void gemm_w(const bf16* __restrict__ Ahi_, const bf16* __restrict__ Alo_,
            const bf16* __restrict__ Whi_, const bf16* __restrict__ Wlo_,
            const float* __restrict__ bias_, float* __restrict__ Cf_,
            bf16* __restrict__ Chi_, bf16* __restrict__ Clo_,
            size_t sA, size_t sW, size_t sB, size_t sC) {
    extern __shared__ char smraw[];
    const int z = blockIdx.z;
    const bf16* Ahi = Ahi_ + (size_t)z * sA;
    const bf16* Alo = Alo_ + (size_t)z * sA;
    const bf16* Whi = Whi_ + (size_t)z * sW;
    const bf16* Wlo = Wlo_ + (size_t)z * sW;
    const float* bias = bias_ + (size_t)z * sB;
    float* Cf = WF32 ? Cf_ + (size_t)z * sC : nullptr;
    bf16* Chi = WSPLIT ? Chi_ + (size_t)z * sC : nullptr;
    bf16* Clo = WSPLIT ? Clo_ + (size_t)z * sC : nullptr;

    const int tid = threadIdx.x, wid = tid >> 5, lane = tid & 31;
    const int wm = wid >> 1, wn = wid & 1;
    const int m0 = blockIdx.y * 128, n0 = blockIdx.x * 128;

    wmma::fragment<wmma::accumulator, 16, 16, 16, float> acc[4][4];
    #pragma unroll
    for (int i = 0; i < 4; i++)
        #pragma unroll
        for (int j = 0; j < 4; j++)
            wmma::fill_fragment(acc[i][j], 0.0f);

    auto load_stage = [&](int st, int kt) {
        bf16* Ah = reinterpret_cast<bf16*>(smraw + st * GSTGB);
        bf16* Al = Ah + 128 * LDK;
        bf16* Bh = Al + 128 * LDK;
        bf16* Bl = Bh + 128 * LDK;
        const int k0 = kt * BK;
        #pragma unroll
        for (int t = 0; t < 4; t++) {
            int item = tid + t * 128;
            int r = item >> 2, c = (item & 3) * 8;
            size_t ga = (size_t)(m0 + r) * Dd + k0 + c;
            size_t gb = (size_t)(n0 + r) * Dd + k0 + c;
            cp16(Ah + r * LDK + c, Ahi + ga);
            cp16(Al + r * LDK + c, Alo + ga);
            cp16(Bh + r * LDK + c, Whi + gb);
            cp16(Bl + r * LDK + c, Wlo + gb);
        }
        cp_commit();
    };

    load_stage(0, 0);
    for (int kt = 0; kt < NKT; kt++) {
        int st = kt & 1;
        if (kt + 1 < NKT) { load_stage(st ^ 1, kt + 1); cp_wait<1>(); }
        else              { cp_wait<0>(); }
        __syncthreads();

        bf16* Ah = reinterpret_cast<bf16*>(smraw + st * GSTGB);
        bf16* Al = Ah + 128 * LDK;
        bf16* Bh = Al + 128 * LDK;
        bf16* Bl = Bh + 128 * LDK;
        #pragma unroll
        for (int ks = 0; ks < BK; ks += 16) {
            wmma::fragment<wmma::matrix_b, 16, 16, 16, bf16, wmma::col_major> bh[4], bl[4];
            #pragma unroll
            for (int j = 0; j < 4; j++) {
                wmma::load_matrix_sync(bh[j], &Bh[(wn * 64 + j * 16) * LDK + ks], LDK);
                wmma::load_matrix_sync(bl[j], &Bl[(wn * 64 + j * 16) * LDK + ks], LDK);
            }
            #pragma unroll
            for (int i = 0; i < 4; i++) {
                wmma::fragment<wmma::matrix_a, 16, 16, 16, bf16, wmma::row_major> ah, al;
                wmma::load_matrix_sync(ah, &Ah[(wm * 64 + i * 16) * LDK + ks], LDK);
                wmma::load_matrix_sync(al, &Al[(wm * 64 + i * 16) * LDK + ks], LDK);
                #pragma unroll
                for (int j = 0; j < 4; j++) {
                    wmma::mma_sync(acc[i][j], ah, bh[j], acc[i][j]);
                    wmma::mma_sync(acc[i][j], ah, bl[j], acc[i][j]);
                    wmma::mma_sync(acc[i][j], al, bh[j], acc[i][j]);
                }
            }
        }
        __syncthreads();
    }

    __syncthreads();
    float* patch = reinterpret_cast<float*>(smraw) + wid * 16 * 20;
    const int er = lane >> 1, eh = (lane & 1) * 8;
    #pragma unroll
    for (int i = 0; i < 4; i++) {
        #pragma unroll
        for (int j = 0; j < 4; j++) {
            wmma::store_matrix_sync(patch, acc[i][j], 20, wmma::mem_row_major);
            __syncwarp();
            int gr = m0 + wm * 64 + i * 16 + er;
            int gc = n0 + wn * 64 + j * 16 + eh;
            size_t go = (size_t)gr * Dd + gc;
            float4 b0 = *reinterpret_cast<const float4*>(&bias[gc]);
            float4 b1 = *reinterpret_cast<const float4*>(&bias[gc + 4]);
            float v[8];
            #pragma unroll
            for (int e = 0; e < 8; e++) v[e] = patch[er * 20 + eh + e];
            v[0] += b0.x; v[1] += b0.y; v[2] += b0.z; v[3] += b0.w;
            v[4] += b1.x; v[5] += b1.y; v[6] += b1.z; v[7] += b1.w;
            if (ACC) {
                float4 o0 = *reinterpret_cast<const float4*>(&Cf[go]);
                float4 o1 = *reinterpret_cast<const float4*>(&Cf[go + 4]);
                v[0] += o0.x; v[1] += o0.y; v[2] += o0.z; v[3] += o0.w;
                v[4] += o1.x; v[5] += o1.y; v[6] += o1.z; v[7] += o1.w;
            }
            if (WF32) {
                *reinterpret_cast<float4*>(&Cf[go])     = *reinterpret_cast<float4*>(&v[0]);
                *reinterpret_cast<float4*>(&Cf[go + 4]) = *reinterpret_cast<float4*>(&v[4]);
            }
            if (WSPLIT) {
                bf16 hs[8], ls[8];
                #pragma unroll
                for (int e = 0; e < 8; e++) split1(v[e], &hs[e], &ls[e]);
                *reinterpret_cast<float4*>(&Chi[go]) = *reinterpret_cast<float4*>(hs);
                *reinterpret_cast<float4*>(&Clo[go]) = *reinterpret_cast<float4*>(ls);
            }
            __syncwarp();
        }
    }
}

// ---------------------------------------------------------------------------
// Fused minicolumn kernel (unchanged from round 5, passing)
// ---------------------------------------------------------------------------
__global__ __launch_bounds__(128, 2)
void fused_w(const bf16* __restrict__ Ahi, const bf16* __restrict__ Alo,
             const bf16* __restrict__ Weh, const bf16* __restrict__ Wel,
             const bf16* __restrict__ Wih, const bf16* __restrict__ Wil,
             const float* __restrict__ be_l, const float* __restrict__ bi_l,
             const float* __restrict__ Wl_l, const float* __restrict__ bl_l,
             bf16* __restrict__ Mhi, bf16* __restrict__ Mlo) {
    extern __shared__ char smraw[];
    __shared__ float swl[1024];
    __shared__ float sbe[64], sbi[64], sbl[64];

    const int tid = threadIdx.x, wid = tid >> 5, lane = tid & 31;
    const int wm = wid >> 1, wn = wid & 1;
    const int m0 = blockIdx.y * 128, n0 = blockIdx.x * 64;

    for (int i = tid; i < 256; i += 128)
        *reinterpret_cast<float4*>(&swl[i * 4]) =
            *reinterpret_cast<const float4*>(&Wl_l[(size_t)n0 * Hh + i * 4]);
    if (tid < 64) {
        sbe[tid] = be_l[n0 + tid];
        sbi[tid] = bi_l[n0 + tid];
        sbl[tid] = bl_l[n0 + tid];
    }

    wmma::fragment<wmma::accumulator, 16, 16, 16, float> ae[4][2], ai[4][2];
    #pragma unroll
    for (int i = 0; i < 4; i++)
        #pragma unroll
        for (int j = 0; j < 2; j++) {
            wmma::fill_fragment(ae[i][j], 0.0f);
            wmma::fill_fragment(ai[i][j], 0.0f);
        }

    auto load_stage = [&](int st, int kt) {
        bf16* Ah = reinterpret_cast<bf16*>(smraw + st * FSTGB);
        bf16* Al = Ah + 128 * LDK;
        bf16* Eh = Al + 128 * LDK;
        bf16* El = Eh + 64 * LDK;
        bf16* Ih = El + 64 * LDK;
        bf16* Il = Ih + 64 * LDK;
        const int k0 = kt * BK;
        #pragma unroll
        for (int t = 0; t < 4; t++) {
            int item = tid + t * 128;
            int r = item >> 2, c = (item & 3) * 8;
            size_t ga = (size_t)(m0 + r) * Dd + k0 + c;
            cp16(Ah + r * LDK + c, Ahi + ga);
            cp16(Al + r * LDK + c, Alo + ga);
        }
        #pragma unroll
        for (int t = 0; t < 2; t++) {
            int item = tid + t * 128;
            int r = item >> 2, c = (item & 3) * 8;
            size_t gb = (size_t)(n0 + r) * Dd + k0 + c;
            cp16(Eh + r * LDK + c, Weh + gb);
            cp16(El + r * LDK + c, Wel + gb);
            cp16(Ih + r * LDK + c, Wih + gb);
            cp16(Il + r * LDK + c, Wil + gb);
        }
        cp_commit();
    };

    load_stage(0, 0);
    for (int kt = 0; kt < NKT; kt++) {
        int st = kt & 1;
        if (kt + 1 < NKT) { load_stage(st ^ 1, kt + 1); cp_wait<1>(); }
        else              { cp_wait<0>(); }
        __syncthreads();

        bf16* Ah = reinterpret_cast<bf16*>(smraw + st * FSTGB);
        bf16* Al = Ah + 128 * LDK;
        bf16* Eh = Al + 128 * LDK;
        bf16* El = Eh + 64 * LDK;
        bf16* Ih = El + 64 * LDK;
        bf16* Il = Ih + 64 * LDK;
        #pragma unroll
        for (int ks = 0; ks < BK; ks += 16) {
            wmma::fragment<wmma::matrix_b, 16, 16, 16, bf16, wmma::col_major>
                eh[2], el[2], ih[2], il[2];
            #pragma unroll
            for (int j = 0; j < 2; j++) {
                int nb = (wn * 32 + j * 16) * LDK + ks;
                wmma::load_matrix_sync(eh[j], &Eh[nb], LDK);
                wmma::load_matrix_sync(el[j], &El[nb], LDK);
                wmma::load_matrix_sync(ih[j], &Ih[nb], LDK);
                wmma::load_matrix_sync(il[j], &Il[nb], LDK);
            }
            #pragma unroll
            for (int i = 0; i < 4; i++) {
                wmma::fragment<wmma::matrix_a, 16, 16, 16, bf16, wmma::row_major> ah, al;
                wmma::load_matrix_sync(ah, &Ah[(wm * 64 + i * 16) * LDK + ks], LDK);
                wmma::load_matrix_sync(al, &Al[(wm * 64 + i * 16) * LDK + ks], LDK);
                #pragma unroll
                for (int j = 0; j < 2; j++) {
                    wmma::mma_sync(ae[i][j], ah, eh[j], ae[i][j]);
                    wmma::mma_sync(ae[i][j], ah, el[j], ae[i][j]);
                    wmma::mma_sync(ae[i][j], al, eh[j], ae[i][j]);
                    wmma::mma_sync(ai[i][j], ah, ih[j], ai[i][j]);
                    wmma::mma_sync(ai[i][j], ah, il[j], ai[i][j]);
                    wmma::mma_sync(ai[i][j], al, ih[j], ai[i][j]);
                }
            }
        }
        __syncthreads();
    }

    __syncthreads();
    float* pe = reinterpret_cast<float*>(smraw) + wid * 2 * 16 * 20;
    float* pi = pe + 16 * 20;
    const int er = lane >> 1, eh8 = (lane & 1) * 8;
    #pragma unroll
    for (int i = 0; i < 4; i++) {
        #pragma unroll
        for (int j = 0; j < 2; j++) {
            wmma::store_matrix_sync(pe, ae[i][j], 20, wmma::mem_row_major);
            wmma::store_matrix_sync(pi, ai[i][j], 20, wmma::mem_row_major);
            __syncwarp();
            int ml = wn * 2 + j;
            int gr = m0 + wm * 64 + i * 16 + er;
            float ihv[16];
            #pragma unroll
            for (int h = 0; h < 16; h++)
                ihv[h] = fmaxf(pi[er * 20 + h] + sbi[ml * 16 + h], 0.0f);
            bf16 hs[8], ls[8];
            #pragma unroll
            for (int e = 0; e < 8; e++) {
                int k = eh8 + e;
                float lat = sbl[ml * 16 + k];
                #pragma unroll
                for (int h = 0; h < 16; h++)
                    lat += ihv[h] * swl[ml * 256 + h * 16 + k];
                float ex = fmaxf(pe[er * 20 + k] + sbe[ml * 16 + k], 0.0f);
                split1(fmaxf(ex - lat, 0.0f), &hs[e], &ls[e]);
            }
            size_t go = (size_t)gr * Dd + n0 + ml * 16 + eh8;
            *reinterpret_cast<float4*>(&Mhi[go]) = *reinterpret_cast<float4*>(hs);
            *reinterpret_cast<float4*>(&Mlo[go]) = *reinterpret_cast<float4*>(ls);
            __syncwarp();
        }
    }
}

// ---------------------------------------------------------------------------
// Host orchestration
// ---------------------------------------------------------------------------
extern "C" void kernel_launch(void* const* d_in, const int* in_sizes, int n_in,
                              void* d_out, int out_size) {
    const float* x    = (const float*)d_in[0];
    const float* We   = (const float*)d_in[1];
    const float* be   = (const float*)d_in[2];
    const float* Wi   = (const float*)d_in[3];
    const float* bi   = (const float*)d_in[4];
    const float* Wl   = (const float*)d_in[5];
    const float* bl   = (const float*)d_in[6];
    const float* Wlat = (const float*)d_in[7];
    const float* blat = (const float*)d_in[8];
    const float* Wv   = (const float*)d_in[9];
    const float* bv   = (const float*)d_in[10];
    const float* Wo   = (const float*)d_in[11];
    const float* bo   = (const float*)d_in[12];
    const float* fbW  = (const float*)d_in[13];
    const float* fbb  = (const float*)d_in[14];
    float* out = (float*)d_out;

    bf16 *wc_h, *wc_l, *wv_h, *wv_l, *wo_h, *wo_l, *fb_h, *fb_l;
    bf16 *we_h, *we_l, *wi_h, *wi_l, *a0h, *a0l, *a1h, *a1l;
    bf16 *s1h, *s1l, *s2h, *s2l;
    float *t2, *bc1, *bc2, *zero;
    cudaGetSymbolAddress((void**)&wc_h, g_wc_h);
    cudaGetSymbolAddress((void**)&wc_l, g_wc_l);
    cudaGetSymbolAddress((void**)&wv_h, g_wv_h);
    cudaGetSymbolAddress((void**)&wv_l, g_wv_l);
    cudaGetSymbolAddress((void**)&wo_h, g_wo_h);
    cudaGetSymbolAddress((void**)&wo_l, g_wo_l);
    cudaGetSymbolAddress((void**)&fb_h, g_fb_h);
    cudaGetSymbolAddress((void**)&fb_l, g_fb_l);
    cudaGetSymbolAddress((void**)&we_h, g_we_h);
    cudaGetSymbolAddress((void**)&we_l, g_we_l);
    cudaGetSymbolAddress((void**)&wi_h, g_wi_h);
    cudaGetSymbolAddress((void**)&wi_l, g_wi_l);
    cudaGetSymbolAddress((void**)&a0h,  g_a0h);
    cudaGetSymbolAddress((void**)&a0l,  g_a0l);
    cudaGetSymbolAddress((void**)&a1h,  g_a1h);
    cudaGetSymbolAddress((void**)&a1l,  g_a1l);
    cudaGetSymbolAddress((void**)&s1h,  g_s1h);
    cudaGetSymbolAddress((void**)&s1l,  g_s1l);
    cudaGetSymbolAddress((void**)&s2h,  g_s2h);
    cudaGetSymbolAddress((void**)&s2l,  g_s2l);
    cudaGetSymbolAddress((void**)&t2,   g_t2);
    cudaGetSymbolAddress((void**)&bc1,  g_bc1);
    cudaGetSymbolAddress((void**)&bc2,  g_bc2);
    cudaGetSymbolAddress((void**)&zero, g_zero);

    cudaFuncSetAttribute(gemm_w<false, false, true>, cudaFuncAttributeMaxDynamicSharedMemorySize, GDSM);
    cudaFuncSetAttribute(gemm_w<false, true, false>, cudaFuncAttributeMaxDynamicSharedMemorySize, GDSM);
    cudaFuncSetAttribute(gemm_w<false, true, true>,  cudaFuncAttributeMaxDynamicSharedMemorySize, GDSM);
    cudaFuncSetAttribute(gemm_w<true, true, true>,   cudaFuncAttributeMaxDynamicSharedMemorySize, GDSM);
    cudaFuncSetAttribute(fused_w,                    cudaFuncAttributeMaxDynamicSharedMemorySize, FDSM);

    // --- One-time conversions ---
    conv_T<<<dim3(32, 32, 6), 256>>>(Wv,  wv_h, wv_l);
    conv_T<<<dim3(32, 32, 6), 256>>>(Wo,  wo_h, wo_l);
    conv_T<<<dim3(32, 32, 5), 256>>>(fbW, fb_h, fb_l);
    conv_gT<<<dim3(16, 64, 6), 256>>>(We, we_h, we_l);
    conv_gT<<<dim3(16, 64, 6), 256>>>(Wi, wi_h, wi_l);
    conv_act<<<6 * M1 / 4 / 256, 256>>>(Wlat, s1h, s1l);   // Wlat split row-major
    conv_act<<<(int)(BD / 4 / 256), 256>>>(x, a1h, a1l);

    // --- Combo precompute: W_combo = Wlat @ Wv @ Wo ; b_combo ---
    dim3 gridC(8, 8, 6);
    // T1 = Wlat @ Wv  (split output only)
    gemm_w<false, false, true><<<gridC, 128, GDSM>>>(s1h, s1l, wv_h, wv_l,
        zero, nullptr, s2h, s2l, M1, M1, 0, M1);
    // combo = T1 @ Wo (fp32 output only)
    gemm_w<false, true, false><<<gridC, 128, GDSM>>>(s2h, s2l, wo_h, wo_l,
        zero, t2, nullptr, nullptr, M1, M1, 0, M1);
    conv_T<<<dim3(32, 32, 6), 256>>>(t2, wc_h, wc_l);
    bias_combo<<<dim3(4, 6), 256>>>(blat, Wv, bv, bc1);
    bias_combo<<<dim3(4, 6), 256>>>(bc1, Wo, bo, bc2);

    const size_t WL_STRIDE = (size_t)NMC * Hh * Hh;
    dim3 gridG(Dd / 128, Bsz / 128, 1);
    dim3 gridF(Dd / 64,  Bsz / 128);

    for (int l = 0; l < Lc; l++) {
        fused_w<<<gridF, 128, FDSM>>>(a1h, a1l,
            we_h + (size_t)l * M1, we_l + (size_t)l * M1,
            wi_h + (size_t)l * M1, wi_l + (size_t)l * M1,
            be + l * Dd, bi + l * Dd, Wl + l * WL_STRIDE, bl + l * Dd,
            a0h, a0l);
        gemm_w<false, true, true><<<gridG, 128, GDSM>>>(a0h, a0l,
            wc_h + (size_t)l * M1, wc_l + (size_t)l * M1,
            bc2 + (size_t)l * Dd, out + (size_t)l * BD, a1h, a1l,
            0, 0, 0, 0);
    }

    int p = 1;
    for (int i = 0; i < Lc - 1; i++) {
        int idx = Lc - 2 - i;
        bf16* sh = p ? a1h : a0h;
        bf16* sl = p ? a1l : a0l;
        bf16* dh = p ? a0h : a1h;
        bf16* dl = p ? a0l : a1l;
        gemm_w<true, true, true><<<gridG, 128, GDSM>>>(sh, sl,
            fb_h + (size_t)i * M1, fb_l + (size_t)i * M1,
            fbb + i * Dd, out + (size_t)idx * BD, dh, dl,
            0, 0, 0, 0);
        p ^= 1;
    }
}